// round 6
// baseline (speedup 1.0000x reference)
#include <cuda_runtime.h>
#include <cuda_bf16.h>
#include <cstdint>
#include <cstddef>

// Problem constants
#define B_    32
#define C_    384
#define H_    32
#define W_    32
#define HW_   1024
#define HK_   16
#define WK_   16
#define HWK_  256
#define HEADS 6
#define DHEAD 64
#define INNER 384          // HEADS*DHEAD
#define SCALE 0.125f       // DIM_HEAD^-0.5
#define BN_EPS 1e-5f

// ---------------------------------------------------------------------------
// Scratch (static device globals; no runtime allocation allowed)
// ---------------------------------------------------------------------------
__device__ float g_yq [(size_t)B_ * C_ * HW_];    // dw+bn output, Q path   [b][c][pix]
__device__ float g_ykv[(size_t)B_ * C_ * HWK_];   // dw+bn output, KV path  [b][c][pix]
__device__ float g_Q  [(size_t)B_ * HW_ * INNER]; // Q projection  [n][384]
__device__ float g_KV [(size_t)B_ * HWK_ * 2 * INNER]; // KV projection [n][768]
__device__ float g_O  [(size_t)B_ * HW_ * INNER]; // attention out [n][384]

// ---------------------------------------------------------------------------
// Kernel 1: fused depthwise 3x3 (+BN) for BOTH Q (stride 1) and KV (stride 2)
// One block per (b, c) plane. Plane staged in smem once.
// ---------------------------------------------------------------------------
__global__ __launch_bounds__(256)
void dwbn_kernel(const float* __restrict__ x,
                 const float* __restrict__ q_dw,  const float* __restrict__ q_gamma,
                 const float* __restrict__ q_beta, const float* __restrict__ q_mean,
                 const float* __restrict__ q_var,
                 const float* __restrict__ kv_dw, const float* __restrict__ kv_gamma,
                 const float* __restrict__ kv_beta, const float* __restrict__ kv_mean,
                 const float* __restrict__ kv_var)
{
    const int c = blockIdx.x;
    const int b = blockIdx.y;
    const int tid = threadIdx.x;

    __shared__ float sx[34 * 34];

    const float* xp = x + ((size_t)b * C_ + c) * HW_;

    for (int i = tid; i < 34 * 34; i += 256) {
        int r = i / 34, cc = i % 34;
        int iy = r - 1, ix = cc - 1;
        float v = 0.f;
        if (iy >= 0 && iy < 32 && ix >= 0 && ix < 32) v = xp[iy * 32 + ix];
        sx[i] = v;
    }
    __syncthreads();

    // per-channel params
    float wq[9], wk[9];
#pragma unroll
    for (int i = 0; i < 9; ++i) { wq[i] = q_dw[c * 9 + i]; wk[i] = kv_dw[c * 9 + i]; }
    const float invq = q_gamma[c] * rsqrtf(q_var[c] + BN_EPS);
    const float addq = q_beta[c] - q_mean[c] * invq;
    const float invk = kv_gamma[c] * rsqrtf(kv_var[c] + BN_EPS);
    const float addk = kv_beta[c] - kv_mean[c] * invk;

    // Q path: 1024 outputs, stride 1
    float* yq = g_yq + ((size_t)b * C_ + c) * HW_;
#pragma unroll
    for (int p = tid; p < HW_; p += 256) {
        int oy = p >> 5, ox = p & 31;
        float s = 0.f;
#pragma unroll
        for (int r = 0; r < 3; ++r)
#pragma unroll
            for (int ss = 0; ss < 3; ++ss)
                s += wq[r * 3 + ss] * sx[(oy + r) * 34 + ox + ss];
        yq[p] = s * invq + addq;
    }

    // KV path: 256 outputs, stride 2 (input window starts at 2*o - 1)
    float* yk = g_ykv + ((size_t)b * C_ + c) * HWK_;
    if (tid < HWK_) {
        int oy = tid >> 4, ox = tid & 15;
        float s = 0.f;
#pragma unroll
        for (int r = 0; r < 3; ++r)
#pragma unroll
            for (int ss = 0; ss < 3; ++ss)
                s += wk[r * 3 + ss] * sx[(2 * oy + r) * 34 + 2 * ox + ss];
        yk[tid] = s * invk + addk;
    }
}

// ---------------------------------------------------------------------------
// Kernel 2: pointwise-conv GEMM.   Cout(n, m) = sum_k A(k|n) * W(m, k)
//   AKM  : A is K-major per batch:  A[batch*K*HWb + k*HWb + nlocal]
//   !AKM : A is row-major:          A[n*K + k]
//   CCM  : C is channel-major NCHW: Cout[batch*M*HWb + m*HWb + nlocal] (+bias)
//   !CCM : C is row-major:          Cout[n*M + m]
// 128x128x8 tile, 256 threads, 8x8 per thread.
// ---------------------------------------------------------------------------
template <bool AKM, bool CCM>
__global__ __launch_bounds__(256, 2)
void gemm_pw(const float* __restrict__ A, const float* __restrict__ W,
             float* __restrict__ Cout, const float* __restrict__ bias,
             int K, int M, int HWb)
{
    __shared__ float As[8][128];
    __shared__ float Bs[8][128];

    const int tid = threadIdx.x;
    const int n0 = blockIdx.x * 128;
    const int m0 = blockIdx.y * 128;
    const int tx = tid & 15;
    const int ty = tid >> 4;

    const float* Ab = A;
    if (AKM) {
        int batch = n0 / HWb;
        Ab = A + (size_t)batch * K * HWb + (n0 % HWb);
    }

    float acc[8][8];
#pragma unroll
    for (int i = 0; i < 8; ++i)
#pragma unroll
        for (int j = 0; j < 8; ++j) acc[i][j] = 0.f;

    for (int k0 = 0; k0 < K; k0 += 8) {
        if (AKM) {
            int kk = tid >> 5, nn = (tid & 31) << 2;
            float4 a4 = *reinterpret_cast<const float4*>(Ab + (size_t)(k0 + kk) * HWb + nn);
            As[kk][nn] = a4.x; As[kk][nn + 1] = a4.y; As[kk][nn + 2] = a4.z; As[kk][nn + 3] = a4.w;
        } else {
            int nn = tid >> 1, kq = (tid & 1) << 2;
            float4 a4 = *reinterpret_cast<const float4*>(A + (size_t)(n0 + nn) * K + k0 + kq);
            As[kq][nn] = a4.x; As[kq + 1][nn] = a4.y; As[kq + 2][nn] = a4.z; As[kq + 3][nn] = a4.w;
        }
        {
            int mm = tid >> 1, kq = (tid & 1) << 2;
            float4 b4 = *reinterpret_cast<const float4*>(W + (size_t)(m0 + mm) * K + k0 + kq);
            Bs[kq][mm] = b4.x; Bs[kq + 1][mm] = b4.y; Bs[kq + 2][mm] = b4.z; Bs[kq + 3][mm] = b4.w;
        }
        __syncthreads();
#pragma unroll
        for (int kk = 0; kk < 8; ++kk) {
            float pa[8], pb[8];
#pragma unroll
            for (int i = 0; i < 8; ++i) pa[i] = CCM ? Bs[kk][ty * 8 + i] : As[kk][ty * 8 + i];
#pragma unroll
            for (int j = 0; j < 8; ++j) pb[j] = CCM ? As[kk][tx * 8 + j] : Bs[kk][tx * 8 + j];
#pragma unroll
            for (int i = 0; i < 8; ++i)
#pragma unroll
                for (int j = 0; j < 8; ++j) acc[i][j] += pa[i] * pb[j];
        }
        __syncthreads();
    }

    if (!CCM) {
        // row-major: rows = n (ty), cols = m (tx, contiguous)
#pragma unroll
        for (int i = 0; i < 8; ++i) {
            size_t row = (size_t)(n0 + ty * 8 + i) * M + m0 + tx * 8;
            float4 v0 = make_float4(acc[i][0], acc[i][1], acc[i][2], acc[i][3]);
            float4 v1 = make_float4(acc[i][4], acc[i][5], acc[i][6], acc[i][7]);
            *reinterpret_cast<float4*>(Cout + row) = v0;
            *reinterpret_cast<float4*>(Cout + row + 4) = v1;
        }
    } else {
        // channel-major NCHW: rows = m (ty), cols = n (tx, contiguous spatial)
        int batch = n0 / HWb;
        int nl0 = n0 % HWb;
#pragma unroll
        for (int i = 0; i < 8; ++i) {
            int m = m0 + ty * 8 + i;
            float bv = bias ? bias[m] : 0.f;
            size_t base = ((size_t)batch * M + m) * HWb + nl0 + tx * 8;
            float4 v0 = make_float4(acc[i][0] + bv, acc[i][1] + bv, acc[i][2] + bv, acc[i][3] + bv);
            float4 v1 = make_float4(acc[i][4] + bv, acc[i][5] + bv, acc[i][6] + bv, acc[i][7] + bv);
            *reinterpret_cast<float4*>(Cout + base) = v0;
            *reinterpret_cast<float4*>(Cout + base + 4) = v1;
        }
    }
}

// ---------------------------------------------------------------------------
// Kernel 3: attention. grid (qchunk=4, head=6, batch=32), 256 threads.
// K/V for (b,h) resident in smem; each warp processes 4 queries at a time,
// exact softmax (store exp(s-m) in smem, normalize at the end).
// smem: K_s [64][257] (d-major, padded) | V_s [256][64] | q_s 8*4*64 | p_s 8*4*256
// ---------------------------------------------------------------------------
#define KS_FLOATS (64 * 257)
#define VS_FLOATS (256 * 64)
#define QS_FLOATS (8 * 4 * 64)
#define PS_FLOATS (8 * 4 * 256)
#define ATTN_SMEM_BYTES ((KS_FLOATS + VS_FLOATS + QS_FLOATS + PS_FLOATS) * 4)

__global__ __launch_bounds__(256)
void attn_kernel()
{
    extern __shared__ float sm[];
    float* K_s = sm;
    float* V_s = K_s + KS_FLOATS;
    float* q_s = V_s + VS_FLOATS;
    float* p_s = q_s + QS_FLOATS;

    const int qc = blockIdx.x;   // 0..3
    const int h  = blockIdx.y;   // 0..5
    const int b  = blockIdx.z;   // 0..31
    const int tid = threadIdx.x;

    // stage K (transposed, padded) and V (row-major) into smem
    for (int idx = tid; idx < 256 * 64; idx += 256) {
        int j = idx >> 6, dd = idx & 63;
        const float* kvp = g_KV + ((size_t)(b * HWK_ + j)) * (2 * INNER) + h * DHEAD;
        K_s[dd * 257 + j] = kvp[dd];
        V_s[idx]          = kvp[INNER + dd];
    }
    __syncthreads();

    const int w = tid >> 5;
    const int lane = tid & 31;
    float* qw = q_s + w * 256;   // 4 queries x 64 dims
    float* pw = p_s + w * 1024;  // 4 queries x 256 probs

    for (int it = 0; it < 8; ++it) {
        const int qg = qc * 256 + (it * 8 + w) * 4;  // base of 4 queries

        // cooperative load of 4 q vectors
        const float* qbase = g_Q + ((size_t)b * HW_ + qg) * INNER + h * DHEAD;
#pragma unroll
        for (int r = 0; r < 8; ++r) {
            int e = r * 32 + lane;       // 0..255
            int qn = e >> 6, dd = e & 63;
            qw[e] = qbase[(size_t)qn * INNER + dd];
        }
        __syncwarp();

        // QK^T: each lane owns keys j = jj*32+lane
        float s[4][8];
#pragma unroll
        for (int qn = 0; qn < 4; ++qn)
#pragma unroll
            for (int jj = 0; jj < 8; ++jj) s[qn][jj] = 0.f;

#pragma unroll 4
        for (int d = 0; d < 64; ++d) {
            float q0 = qw[d], q1 = qw[64 + d], q2 = qw[128 + d], q3 = qw[192 + d];
            const float* krow = K_s + d * 257 + lane;
#pragma unroll
            for (int jj = 0; jj < 8; ++jj) {
                float kv = krow[jj * 32];
                s[0][jj] += q0 * kv;
                s[1][jj] += q1 * kv;
                s[2][jj] += q2 * kv;
                s[3][jj] += q3 * kv;
            }
        }

        // softmax (exact; p stored to smem, normalized at the end)
        float linv[4];
#pragma unroll
        for (int qn = 0; qn < 4; ++qn) {
            float m = -1e30f;
#pragma unroll
            for (int jj = 0; jj < 8; ++jj) {
                s[qn][jj] *= SCALE;
                m = fmaxf(m, s[qn][jj]);
            }
#pragma unroll
            for (int o = 16; o > 0; o >>= 1)
                m = fmaxf(m, __shfl_xor_sync(0xffffffffu, m, o));
            float l = 0.f;
#pragma unroll
            for (int jj = 0; jj < 8; ++jj) {
                float p = __expf(s[qn][jj] - m);
                pw[qn * 256 + jj * 32 + lane] = p;
                l += p;
            }
#pragma unroll
            for (int o = 16; o > 0; o >>= 1)
                l += __shfl_xor_sync(0xffffffffu, l, o);
            linv[qn] = 1.0f / l;
        }
        __syncwarp();

        // P @ V : lane owns dims {lane, lane+32}
        float acc[4][2];
#pragma unroll
        for (int qn = 0; qn < 4; ++qn) { acc[qn][0] = 0.f; acc[qn][1] = 0.f; }

#pragma unroll 4
        for (int j = 0; j < 256; ++j) {
            float v0 = V_s[j * 64 + lane];
            float v1 = V_s[j * 64 + 32 + lane];
#pragma unroll
            for (int qn = 0; qn < 4; ++qn) {
                float p = pw[qn * 256 + j];
                acc[qn][0] += p * v0;
                acc[qn][1] += p * v1;
            }
        }

#pragma unroll
        for (int qn = 0; qn < 4; ++qn) {
            size_t o = ((size_t)b * HW_ + qg + qn) * INNER + h * DHEAD;
            g_O[o + lane]      = acc[qn][0] * linv[qn];
            g_O[o + 32 + lane] = acc[qn][1] * linv[qn];
        }
        __syncwarp();
    }
}

// ---------------------------------------------------------------------------
// launcher
// ---------------------------------------------------------------------------
extern "C" void kernel_launch(void* const* d_in, const int* in_sizes, int n_in,
                              void* d_out, int out_size)
{
    (void)in_sizes; (void)n_in; (void)out_size;

    const float* x        = (const float*)d_in[0];
    const float* q_dw     = (const float*)d_in[1];
    const float* q_gamma  = (const float*)d_in[2];
    const float* q_beta   = (const float*)d_in[3];
    const float* q_mean   = (const float*)d_in[4];
    const float* q_var    = (const float*)d_in[5];
    const float* q_pw     = (const float*)d_in[6];
    const float* kv_dw    = (const float*)d_in[7];
    const float* kv_gamma = (const float*)d_in[8];
    const float* kv_beta  = (const float*)d_in[9];
    const float* kv_mean  = (const float*)d_in[10];
    const float* kv_var   = (const float*)d_in[11];
    const float* kv_pw    = (const float*)d_in[12];
    const float* out_w    = (const float*)d_in[13];
    const float* out_b    = (const float*)d_in[14];
    float* out = (float*)d_out;

    // resolve scratch symbols
    void *p_yq, *p_ykv, *p_Q, *p_KV, *p_O;
    cudaGetSymbolAddress(&p_yq,  g_yq);
    cudaGetSymbolAddress(&p_ykv, g_ykv);
    cudaGetSymbolAddress(&p_Q,   g_Q);
    cudaGetSymbolAddress(&p_KV,  g_KV);
    cudaGetSymbolAddress(&p_O,   g_O);

    // 1) depthwise conv + BN (both paths)
    dwbn_kernel<<<dim3(C_, B_), 256>>>(x,
        q_dw, q_gamma, q_beta, q_mean, q_var,
        kv_dw, kv_gamma, kv_beta, kv_mean, kv_var);

    // 2) Q pointwise:  [32768, 384] = yq(K-major) x q_pw
    gemm_pw<true, false><<<dim3((B_ * HW_) / 128, INNER / 128), 256>>>(
        (const float*)p_yq, q_pw, (float*)p_Q, nullptr, C_, INNER, HW_);

    // 3) KV pointwise: [8192, 768] = ykv(K-major) x kv_pw
    gemm_pw<true, false><<<dim3((B_ * HWK_) / 128, (2 * INNER) / 128), 256>>>(
        (const float*)p_ykv, kv_pw, (float*)p_KV, nullptr, C_, 2 * INNER, HWK_);

    // 4) attention
    cudaFuncSetAttribute(attn_kernel,
                         cudaFuncAttributeMaxDynamicSharedMemorySize,
                         ATTN_SMEM_BYTES);
    attn_kernel<<<dim3(4, HEADS, B_), 256, ATTN_SMEM_BYTES>>>();

    // 5) output projection -> NCHW with bias
    gemm_pw<false, true><<<dim3((B_ * HW_) / 128, C_ / 128), 256>>>(
        (const float*)p_O, out_w, out, out_b, INNER, C_, HW_);
}

// round 7
// speedup vs baseline: 1.0011x; 1.0011x over previous
#include <cuda_runtime.h>
#include <cuda_bf16.h>
#include <cstdint>
#include <cstddef>

// Problem constants
#define B_    32
#define C_    384
#define H_    32
#define W_    32
#define HW_   1024
#define HK_   16
#define WK_   16
#define HWK_  256
#define HEADS 6
#define DHEAD 64
#define INNER 384          // HEADS*DHEAD
#define SCALE 0.125f       // DIM_HEAD^-0.5
#define BN_EPS 1e-5f

// ---------------------------------------------------------------------------
// Scratch (static device globals; no runtime allocation allowed)
// ---------------------------------------------------------------------------
__device__ float g_yq [(size_t)B_ * C_ * HW_];    // dw+bn output, Q path   [b][c][pix]
__device__ float g_ykv[(size_t)B_ * C_ * HWK_];   // dw+bn output, KV path  [b][c][pix]
__device__ float g_Q  [(size_t)B_ * HW_ * INNER]; // Q projection  [n][384]
__device__ float g_KV [(size_t)B_ * HWK_ * 2 * INNER]; // KV projection [n][768]
__device__ float g_O  [(size_t)B_ * HW_ * INNER]; // attention out [n][384]

// ---------------------------------------------------------------------------
// Kernel 1: fused depthwise 3x3 (+BN) for BOTH Q (stride 1) and KV (stride 2)
// One block per (b, c) plane. Plane staged in smem once.
// ---------------------------------------------------------------------------
__global__ __launch_bounds__(256)
void dwbn_kernel(const float* __restrict__ x,
                 const float* __restrict__ q_dw,  const float* __restrict__ q_gamma,
                 const float* __restrict__ q_beta, const float* __restrict__ q_mean,
                 const float* __restrict__ q_var,
                 const float* __restrict__ kv_dw, const float* __restrict__ kv_gamma,
                 const float* __restrict__ kv_beta, const float* __restrict__ kv_mean,
                 const float* __restrict__ kv_var)
{
    const int c = blockIdx.x;
    const int b = blockIdx.y;
    const int tid = threadIdx.x;

    __shared__ float sx[34 * 34];

    const float* xp = x + ((size_t)b * C_ + c) * HW_;

    for (int i = tid; i < 34 * 34; i += 256) {
        int r = i / 34, cc = i % 34;
        int iy = r - 1, ix = cc - 1;
        float v = 0.f;
        if (iy >= 0 && iy < 32 && ix >= 0 && ix < 32) v = xp[iy * 32 + ix];
        sx[i] = v;
    }
    __syncthreads();

    // per-channel params
    float wq[9], wk[9];
#pragma unroll
    for (int i = 0; i < 9; ++i) { wq[i] = q_dw[c * 9 + i]; wk[i] = kv_dw[c * 9 + i]; }
    const float invq = q_gamma[c] * rsqrtf(q_var[c] + BN_EPS);
    const float addq = q_beta[c] - q_mean[c] * invq;
    const float invk = kv_gamma[c] * rsqrtf(kv_var[c] + BN_EPS);
    const float addk = kv_beta[c] - kv_mean[c] * invk;

    // Q path: 1024 outputs, stride 1
    float* yq = g_yq + ((size_t)b * C_ + c) * HW_;
#pragma unroll
    for (int p = tid; p < HW_; p += 256) {
        int oy = p >> 5, ox = p & 31;
        float s = 0.f;
#pragma unroll
        for (int r = 0; r < 3; ++r)
#pragma unroll
            for (int ss = 0; ss < 3; ++ss)
                s += wq[r * 3 + ss] * sx[(oy + r) * 34 + ox + ss];
        yq[p] = s * invq + addq;
    }

    // KV path: 256 outputs, stride 2 (input window starts at 2*o - 1)
    float* yk = g_ykv + ((size_t)b * C_ + c) * HWK_;
    if (tid < HWK_) {
        int oy = tid >> 4, ox = tid & 15;
        float s = 0.f;
#pragma unroll
        for (int r = 0; r < 3; ++r)
#pragma unroll
            for (int ss = 0; ss < 3; ++ss)
                s += wk[r * 3 + ss] * sx[(2 * oy + r) * 34 + 2 * ox + ss];
        yk[tid] = s * invk + addk;
    }
}

// ---------------------------------------------------------------------------
// Kernel 2: pointwise-conv GEMM.   Cout(n, m) = sum_k A(k|n) * W(m, k)
//   AKM  : A is K-major per batch:  A[batch*K*HWb + k*HWb + nlocal]
//   !AKM : A is row-major:          A[n*K + k]
//   CCM  : C is channel-major NCHW: Cout[batch*M*HWb + m*HWb + nlocal] (+bias)
//   !CCM : C is row-major:          Cout[n*M + m]
// 128x128x8 tile, 256 threads, 8x8 per thread.
// ---------------------------------------------------------------------------
template <bool AKM, bool CCM>
__global__ __launch_bounds__(256, 2)
void gemm_pw(const float* __restrict__ A, const float* __restrict__ W,
             float* __restrict__ Cout, const float* __restrict__ bias,
             int K, int M, int HWb)
{
    __shared__ float As[8][128];
    __shared__ float Bs[8][128];

    const int tid = threadIdx.x;
    const int n0 = blockIdx.x * 128;
    const int m0 = blockIdx.y * 128;
    const int tx = tid & 15;
    const int ty = tid >> 4;

    const float* Ab = A;
    if (AKM) {
        int batch = n0 / HWb;
        Ab = A + (size_t)batch * K * HWb + (n0 % HWb);
    }

    float acc[8][8];
#pragma unroll
    for (int i = 0; i < 8; ++i)
#pragma unroll
        for (int j = 0; j < 8; ++j) acc[i][j] = 0.f;

    for (int k0 = 0; k0 < K; k0 += 8) {
        if (AKM) {
            int kk = tid >> 5, nn = (tid & 31) << 2;
            float4 a4 = *reinterpret_cast<const float4*>(Ab + (size_t)(k0 + kk) * HWb + nn);
            As[kk][nn] = a4.x; As[kk][nn + 1] = a4.y; As[kk][nn + 2] = a4.z; As[kk][nn + 3] = a4.w;
        } else {
            int nn = tid >> 1, kq = (tid & 1) << 2;
            float4 a4 = *reinterpret_cast<const float4*>(A + (size_t)(n0 + nn) * K + k0 + kq);
            As[kq][nn] = a4.x; As[kq + 1][nn] = a4.y; As[kq + 2][nn] = a4.z; As[kq + 3][nn] = a4.w;
        }
        {
            int mm = tid >> 1, kq = (tid & 1) << 2;
            float4 b4 = *reinterpret_cast<const float4*>(W + (size_t)(m0 + mm) * K + k0 + kq);
            Bs[kq][mm] = b4.x; Bs[kq + 1][mm] = b4.y; Bs[kq + 2][mm] = b4.z; Bs[kq + 3][mm] = b4.w;
        }
        __syncthreads();
#pragma unroll
        for (int kk = 0; kk < 8; ++kk) {
            float pa[8], pb[8];
#pragma unroll
            for (int i = 0; i < 8; ++i) pa[i] = CCM ? Bs[kk][ty * 8 + i] : As[kk][ty * 8 + i];
#pragma unroll
            for (int j = 0; j < 8; ++j) pb[j] = CCM ? As[kk][tx * 8 + j] : Bs[kk][tx * 8 + j];
#pragma unroll
            for (int i = 0; i < 8; ++i)
#pragma unroll
                for (int j = 0; j < 8; ++j) acc[i][j] += pa[i] * pb[j];
        }
        __syncthreads();
    }

    if (!CCM) {
        // row-major: rows = n (ty), cols = m (tx, contiguous)
#pragma unroll
        for (int i = 0; i < 8; ++i) {
            size_t row = (size_t)(n0 + ty * 8 + i) * M + m0 + tx * 8;
            float4 v0 = make_float4(acc[i][0], acc[i][1], acc[i][2], acc[i][3]);
            float4 v1 = make_float4(acc[i][4], acc[i][5], acc[i][6], acc[i][7]);
            *reinterpret_cast<float4*>(Cout + row) = v0;
            *reinterpret_cast<float4*>(Cout + row + 4) = v1;
        }
    } else {
        // channel-major NCHW: rows = m (ty), cols = n (tx, contiguous spatial)
        int batch = n0 / HWb;
        int nl0 = n0 % HWb;
#pragma unroll
        for (int i = 0; i < 8; ++i) {
            int m = m0 + ty * 8 + i;
            float bv = bias ? bias[m] : 0.f;
            size_t base = ((size_t)batch * M + m) * HWb + nl0 + tx * 8;
            float4 v0 = make_float4(acc[i][0] + bv, acc[i][1] + bv, acc[i][2] + bv, acc[i][3] + bv);
            float4 v1 = make_float4(acc[i][4] + bv, acc[i][5] + bv, acc[i][6] + bv, acc[i][7] + bv);
            *reinterpret_cast<float4*>(Cout + base) = v0;
            *reinterpret_cast<float4*>(Cout + base + 4) = v1;
        }
    }
}

// ---------------------------------------------------------------------------
// Kernel 3: attention. grid (qchunk=4, head=6, batch=32), 256 threads.
// K/V for (b,h) resident in smem; each warp processes 4 queries at a time,
// exact softmax (store exp(s-m) in smem, normalize at the end).
// smem: K_s [64][257] (d-major, padded) | V_s [256][64] | q_s 8*4*64 | p_s 8*4*256
// ---------------------------------------------------------------------------
#define KS_FLOATS (64 * 257)
#define VS_FLOATS (256 * 64)
#define QS_FLOATS (8 * 4 * 64)
#define PS_FLOATS (8 * 4 * 256)
#define ATTN_SMEM_BYTES ((KS_FLOATS + VS_FLOATS + QS_FLOATS + PS_FLOATS) * 4)

__global__ __launch_bounds__(256)
void attn_kernel()
{
    extern __shared__ float sm[];
    float* K_s = sm;
    float* V_s = K_s + KS_FLOATS;
    float* q_s = V_s + VS_FLOATS;
    float* p_s = q_s + QS_FLOATS;

    const int qc = blockIdx.x;   // 0..3
    const int h  = blockIdx.y;   // 0..5
    const int b  = blockIdx.z;   // 0..31
    const int tid = threadIdx.x;

    // stage K (transposed, padded) and V (row-major) into smem
    for (int idx = tid; idx < 256 * 64; idx += 256) {
        int j = idx >> 6, dd = idx & 63;
        const float* kvp = g_KV + ((size_t)(b * HWK_ + j)) * (2 * INNER) + h * DHEAD;
        K_s[dd * 257 + j] = kvp[dd];
        V_s[idx]          = kvp[INNER + dd];
    }
    __syncthreads();

    const int w = tid >> 5;
    const int lane = tid & 31;
    float* qw = q_s + w * 256;   // 4 queries x 64 dims
    float* pw = p_s + w * 1024;  // 4 queries x 256 probs

    for (int it = 0; it < 8; ++it) {
        const int qg = qc * 256 + (it * 8 + w) * 4;  // base of 4 queries

        // cooperative load of 4 q vectors
        const float* qbase = g_Q + ((size_t)b * HW_ + qg) * INNER + h * DHEAD;
#pragma unroll
        for (int r = 0; r < 8; ++r) {
            int e = r * 32 + lane;       // 0..255
            int qn = e >> 6, dd = e & 63;
            qw[e] = qbase[(size_t)qn * INNER + dd];
        }
        __syncwarp();

        // QK^T: each lane owns keys j = jj*32+lane
        float s[4][8];
#pragma unroll
        for (int qn = 0; qn < 4; ++qn)
#pragma unroll
            for (int jj = 0; jj < 8; ++jj) s[qn][jj] = 0.f;

#pragma unroll 4
        for (int d = 0; d < 64; ++d) {
            float q0 = qw[d], q1 = qw[64 + d], q2 = qw[128 + d], q3 = qw[192 + d];
            const float* krow = K_s + d * 257 + lane;
#pragma unroll
            for (int jj = 0; jj < 8; ++jj) {
                float kv = krow[jj * 32];
                s[0][jj] += q0 * kv;
                s[1][jj] += q1 * kv;
                s[2][jj] += q2 * kv;
                s[3][jj] += q3 * kv;
            }
        }

        // softmax (exact; p stored to smem, normalized at the end)
        float linv[4];
#pragma unroll
        for (int qn = 0; qn < 4; ++qn) {
            float m = -1e30f;
#pragma unroll
            for (int jj = 0; jj < 8; ++jj) {
                s[qn][jj] *= SCALE;
                m = fmaxf(m, s[qn][jj]);
            }
#pragma unroll
            for (int o = 16; o > 0; o >>= 1)
                m = fmaxf(m, __shfl_xor_sync(0xffffffffu, m, o));
            float l = 0.f;
#pragma unroll
            for (int jj = 0; jj < 8; ++jj) {
                float p = __expf(s[qn][jj] - m);
                pw[qn * 256 + jj * 32 + lane] = p;
                l += p;
            }
#pragma unroll
            for (int o = 16; o > 0; o >>= 1)
                l += __shfl_xor_sync(0xffffffffu, l, o);
            linv[qn] = 1.0f / l;
        }
        __syncwarp();

        // P @ V : lane owns dims {lane, lane+32}
        float acc[4][2];
#pragma unroll
        for (int qn = 0; qn < 4; ++qn) { acc[qn][0] = 0.f; acc[qn][1] = 0.f; }

#pragma unroll 4
        for (int j = 0; j < 256; ++j) {
            float v0 = V_s[j * 64 + lane];
            float v1 = V_s[j * 64 + 32 + lane];
#pragma unroll
            for (int qn = 0; qn < 4; ++qn) {
                float p = pw[qn * 256 + j];
                acc[qn][0] += p * v0;
                acc[qn][1] += p * v1;
            }
        }

#pragma unroll
        for (int qn = 0; qn < 4; ++qn) {
            size_t o = ((size_t)b * HW_ + qg + qn) * INNER + h * DHEAD;
            g_O[o + lane]      = acc[qn][0] * linv[qn];
            g_O[o + 32 + lane] = acc[qn][1] * linv[qn];
        }
        __syncwarp();
    }
}

// ---------------------------------------------------------------------------
// launcher
// ---------------------------------------------------------------------------
extern "C" void kernel_launch(void* const* d_in, const int* in_sizes, int n_in,
                              void* d_out, int out_size)
{
    (void)in_sizes; (void)n_in; (void)out_size;

    const float* x        = (const float*)d_in[0];
    const float* q_dw     = (const float*)d_in[1];
    const float* q_gamma  = (const float*)d_in[2];
    const float* q_beta   = (const float*)d_in[3];
    const float* q_mean   = (const float*)d_in[4];
    const float* q_var    = (const float*)d_in[5];
    const float* q_pw     = (const float*)d_in[6];
    const float* kv_dw    = (const float*)d_in[7];
    const float* kv_gamma = (const float*)d_in[8];
    const float* kv_beta  = (const float*)d_in[9];
    const float* kv_mean  = (const float*)d_in[10];
    const float* kv_var   = (const float*)d_in[11];
    const float* kv_pw    = (const float*)d_in[12];
    const float* out_w    = (const float*)d_in[13];
    const float* out_b    = (const float*)d_in[14];
    float* out = (float*)d_out;

    // resolve scratch symbols
    void *p_yq, *p_ykv, *p_Q, *p_KV, *p_O;
    cudaGetSymbolAddress(&p_yq,  g_yq);
    cudaGetSymbolAddress(&p_ykv, g_ykv);
    cudaGetSymbolAddress(&p_Q,   g_Q);
    cudaGetSymbolAddress(&p_KV,  g_KV);
    cudaGetSymbolAddress(&p_O,   g_O);

    // 1) depthwise conv + BN (both paths)
    dwbn_kernel<<<dim3(C_, B_), 256>>>(x,
        q_dw, q_gamma, q_beta, q_mean, q_var,
        kv_dw, kv_gamma, kv_beta, kv_mean, kv_var);

    // 2) Q pointwise:  [32768, 384] = yq(K-major) x q_pw
    gemm_pw<true, false><<<dim3((B_ * HW_) / 128, INNER / 128), 256>>>(
        (const float*)p_yq, q_pw, (float*)p_Q, nullptr, C_, INNER, HW_);

    // 3) KV pointwise: [8192, 768] = ykv(K-major) x kv_pw
    gemm_pw<true, false><<<dim3((B_ * HWK_) / 128, (2 * INNER) / 128), 256>>>(
        (const float*)p_ykv, kv_pw, (float*)p_KV, nullptr, C_, 2 * INNER, HWK_);

    // 4) attention
    cudaFuncSetAttribute(attn_kernel,
                         cudaFuncAttributeMaxDynamicSharedMemorySize,
                         ATTN_SMEM_BYTES);
    attn_kernel<<<dim3(4, HEADS, B_), 256, ATTN_SMEM_BYTES>>>();

    // 5) output projection -> NCHW with bias
    gemm_pw<false, true><<<dim3((B_ * HW_) / 128, C_ / 128), 256>>>(
        (const float*)p_O, out_w, out, out_b, INNER, C_, HW_);
}

// round 8
// speedup vs baseline: 1.1963x; 1.1950x over previous
#include <cuda_runtime.h>
#include <cuda_bf16.h>
#include <cstdint>
#include <cstddef>

// Problem constants
#define B_    32
#define C_    384
#define H_    32
#define W_    32
#define HW_   1024
#define HK_   16
#define WK_   16
#define HWK_  256
#define HEADS 6
#define DHEAD 64
#define INNER 384          // HEADS*DHEAD
#define SCALE 0.125f       // DIM_HEAD^-0.5
#define BN_EPS 1e-5f

typedef unsigned long long u64;

// ---------------------------------------------------------------------------
// f32x2 packed-FMA helpers (Blackwell FFMA2 — only reachable via PTX)
// ---------------------------------------------------------------------------
__device__ __forceinline__ void ffma2(u64 &c, u64 a, u64 b) {
    asm("fma.rn.f32x2 %0, %1, %2, %0;" : "+l"(c) : "l"(a), "l"(b));
}
__device__ __forceinline__ u64 pack2(float lo, float hi) {
    u64 r; asm("mov.b64 %0, {%1, %2};" : "=l"(r) : "f"(lo), "f"(hi)); return r;
}
__device__ __forceinline__ float2 unpack2(u64 v) {
    float2 f; asm("mov.b64 {%0, %1}, %2;" : "=f"(f.x), "=f"(f.y) : "l"(v)); return f;
}

// ---------------------------------------------------------------------------
// Scratch (static device globals; no runtime allocation allowed)
// ---------------------------------------------------------------------------
__device__ float g_yq [(size_t)B_ * C_ * HW_];    // dw+bn output, Q path   [b][c][pix]
__device__ float g_ykv[(size_t)B_ * C_ * HWK_];   // dw+bn output, KV path  [b][c][pix]
__device__ float g_Q  [(size_t)B_ * HW_ * INNER]; // Q projection  [n][384]
__device__ float g_KV [(size_t)B_ * HWK_ * 2 * INNER]; // KV projection [n][768]
__device__ float g_O  [(size_t)B_ * HW_ * INNER]; // attention out [n][384]

// ---------------------------------------------------------------------------
// Kernel 1: fused depthwise 3x3 (+BN) for BOTH Q (stride 1) and KV (stride 2)
// ---------------------------------------------------------------------------
__global__ __launch_bounds__(256)
void dwbn_kernel(const float* __restrict__ x,
                 const float* __restrict__ q_dw,  const float* __restrict__ q_gamma,
                 const float* __restrict__ q_beta, const float* __restrict__ q_mean,
                 const float* __restrict__ q_var,
                 const float* __restrict__ kv_dw, const float* __restrict__ kv_gamma,
                 const float* __restrict__ kv_beta, const float* __restrict__ kv_mean,
                 const float* __restrict__ kv_var)
{
    const int c = blockIdx.x;
    const int b = blockIdx.y;
    const int tid = threadIdx.x;

    __shared__ float sx[34 * 34];

    const float* xp = x + ((size_t)b * C_ + c) * HW_;

    for (int i = tid; i < 34 * 34; i += 256) {
        int r = i / 34, cc = i % 34;
        int iy = r - 1, ix = cc - 1;
        float v = 0.f;
        if (iy >= 0 && iy < 32 && ix >= 0 && ix < 32) v = xp[iy * 32 + ix];
        sx[i] = v;
    }
    __syncthreads();

    float wq[9], wk[9];
#pragma unroll
    for (int i = 0; i < 9; ++i) { wq[i] = q_dw[c * 9 + i]; wk[i] = kv_dw[c * 9 + i]; }
    const float invq = q_gamma[c] * rsqrtf(q_var[c] + BN_EPS);
    const float addq = q_beta[c] - q_mean[c] * invq;
    const float invk = kv_gamma[c] * rsqrtf(kv_var[c] + BN_EPS);
    const float addk = kv_beta[c] - kv_mean[c] * invk;

    float* yq = g_yq + ((size_t)b * C_ + c) * HW_;
#pragma unroll
    for (int p = tid; p < HW_; p += 256) {
        int oy = p >> 5, ox = p & 31;
        float s = 0.f;
#pragma unroll
        for (int r = 0; r < 3; ++r)
#pragma unroll
            for (int ss = 0; ss < 3; ++ss)
                s += wq[r * 3 + ss] * sx[(oy + r) * 34 + ox + ss];
        yq[p] = s * invq + addq;
    }

    float* yk = g_ykv + ((size_t)b * C_ + c) * HWK_;
    if (tid < HWK_) {
        int oy = tid >> 4, ox = tid & 15;
        float s = 0.f;
#pragma unroll
        for (int r = 0; r < 3; ++r)
#pragma unroll
            for (int ss = 0; ss < 3; ++ss)
                s += wk[r * 3 + ss] * sx[(2 * oy + r) * 34 + 2 * ox + ss];
        yk[tid] = s * invk + addk;
    }
}

// ---------------------------------------------------------------------------
// Kernel 2: pointwise-conv GEMM with FFMA2 inner loop.
//   AKM  : A is K-major per batch:  A[batch*K*HWb + k*HWb + nlocal]
//   !AKM : A is row-major:          A[n*K + k]
//   CCM  : C is channel-major NCHW: Cout[batch*M*HWb + m*HWb + nlocal] (+bias)
//   !CCM : C is row-major:          Cout[n*M + m]
// 128x128x8 tile, 256 threads, 8x8 per thread; accumulators packed over
// i-pairs in f32x2.
// ---------------------------------------------------------------------------
template <bool AKM, bool CCM>
__global__ __launch_bounds__(256, 2)
void gemm_pw(const float* __restrict__ A, const float* __restrict__ W,
             float* __restrict__ Cout, const float* __restrict__ bias,
             int K, int M, int HWb)
{
    __shared__ float As[8][128];
    __shared__ float Bs[8][128];

    const int tid = threadIdx.x;
    const int n0 = blockIdx.x * 128;
    const int m0 = blockIdx.y * 128;
    const int tx = tid & 15;
    const int ty = tid >> 4;

    const float* Ab = A;
    if (AKM) {
        int batch = n0 / HWb;
        Ab = A + (size_t)batch * K * HWb + (n0 % HWb);
    }

    u64 acc2[4][8];
#pragma unroll
    for (int ip = 0; ip < 4; ++ip)
#pragma unroll
        for (int j = 0; j < 8; ++j) acc2[ip][j] = 0ull;

    for (int k0 = 0; k0 < K; k0 += 8) {
        if (AKM) {
            int kk = tid >> 5, nn = (tid & 31) << 2;
            float4 a4 = *reinterpret_cast<const float4*>(Ab + (size_t)(k0 + kk) * HWb + nn);
            *reinterpret_cast<float4*>(&As[kk][nn]) = a4;
        } else {
            int nn = tid >> 1, kq = (tid & 1) << 2;
            float4 a4 = *reinterpret_cast<const float4*>(A + (size_t)(n0 + nn) * K + k0 + kq);
            As[kq][nn] = a4.x; As[kq + 1][nn] = a4.y; As[kq + 2][nn] = a4.z; As[kq + 3][nn] = a4.w;
        }
        {
            int mm = tid >> 1, kq = (tid & 1) << 2;
            float4 b4 = *reinterpret_cast<const float4*>(W + (size_t)(m0 + mm) * K + k0 + kq);
            Bs[kq][mm] = b4.x; Bs[kq + 1][mm] = b4.y; Bs[kq + 2][mm] = b4.z; Bs[kq + 3][mm] = b4.w;
        }
        __syncthreads();
#pragma unroll
        for (int kk = 0; kk < 8; ++kk) {
            const float* Ar = CCM ? &Bs[kk][0] : &As[kk][0];  // i-axis (rows, ty)
            const float* Br = CCM ? &As[kk][0] : &Bs[kk][0];  // j-axis (cols, tx)

            ulonglong2 aA = *reinterpret_cast<const ulonglong2*>(Ar + ty * 8);
            ulonglong2 aB = *reinterpret_cast<const ulonglong2*>(Ar + ty * 8 + 4);
            u64 a[4] = { aA.x, aA.y, aB.x, aB.y };

            float4 bv0 = *reinterpret_cast<const float4*>(Br + tx * 8);
            float4 bv1 = *reinterpret_cast<const float4*>(Br + tx * 8 + 4);
            float bb[8] = { bv0.x, bv0.y, bv0.z, bv0.w, bv1.x, bv1.y, bv1.z, bv1.w };

#pragma unroll
            for (int j = 0; j < 8; ++j) {
                u64 bd = pack2(bb[j], bb[j]);
                ffma2(acc2[0][j], a[0], bd);
                ffma2(acc2[1][j], a[1], bd);
                ffma2(acc2[2][j], a[2], bd);
                ffma2(acc2[3][j], a[3], bd);
            }
        }
        __syncthreads();
    }

    // unpack to row-wise fp32
    float accr[8][8];
#pragma unroll
    for (int ip = 0; ip < 4; ++ip)
#pragma unroll
        for (int j = 0; j < 8; ++j) {
            float2 f = unpack2(acc2[ip][j]);
            accr[2 * ip][j] = f.x;
            accr[2 * ip + 1][j] = f.y;
        }

    if (!CCM) {
#pragma unroll
        for (int i = 0; i < 8; ++i) {
            size_t row = (size_t)(n0 + ty * 8 + i) * M + m0 + tx * 8;
            float4 v0 = make_float4(accr[i][0], accr[i][1], accr[i][2], accr[i][3]);
            float4 v1 = make_float4(accr[i][4], accr[i][5], accr[i][6], accr[i][7]);
            *reinterpret_cast<float4*>(Cout + row) = v0;
            *reinterpret_cast<float4*>(Cout + row + 4) = v1;
        }
    } else {
        int batch = n0 / HWb;
        int nl0 = n0 % HWb;
#pragma unroll
        for (int i = 0; i < 8; ++i) {
            int m = m0 + ty * 8 + i;
            float bv = bias ? bias[m] : 0.f;
            size_t base = ((size_t)batch * M + m) * HWb + nl0 + tx * 8;
            float4 v0 = make_float4(accr[i][0] + bv, accr[i][1] + bv, accr[i][2] + bv, accr[i][3] + bv);
            float4 v1 = make_float4(accr[i][4] + bv, accr[i][5] + bv, accr[i][6] + bv, accr[i][7] + bv);
            *reinterpret_cast<float4*>(Cout + base) = v0;
            *reinterpret_cast<float4*>(Cout + base + 4) = v1;
        }
    }
}

// ---------------------------------------------------------------------------
// Kernel 3: attention, FFMA2 version.
// grid (qchunk=4, head=6, batch=32), 256 threads (8 warps), 1 block/SM.
// Each warp: 8 queries x 4 iterations. QK accumulates d-pairs in f32x2;
// PV packs query-pairs in f32x2 with p stored interleaved [qpair][j][2].
// smem: K_s [256][68] j-major padded | V_s [256][64] | q_s 8w*512 | p_s 8w*2048
// ---------------------------------------------------------------------------
#define KP 68
#define ATTN_SMEM_FLOATS (256 * KP + 256 * 64 + 8 * 512 + 8 * 2048)
#define ATTN_SMEM_BYTES  (ATTN_SMEM_FLOATS * 4)

__global__ __launch_bounds__(256)
void attn_kernel()
{
    extern __shared__ float sm[];
    float* K_s = sm;                      // [256][KP]
    float* V_s = K_s + 256 * KP;          // [256][64]
    float* q_s = V_s + 256 * 64;          // per warp: 8q x 64d
    float* p_s = q_s + 8 * 512;           // per warp: 4qp x 256j x 2

    const int qc = blockIdx.x;   // 0..3
    const int h  = blockIdx.y;   // 0..5
    const int b  = blockIdx.z;   // 0..31
    const int tid = threadIdx.x;

    // stage K (j-major, padded) and V (j-major) into smem
    for (int idx = tid; idx < 256 * 16; idx += 256) {
        int j = idx >> 4, f = idx & 15;
        const float4* kv = reinterpret_cast<const float4*>(
            g_KV + ((size_t)(b * HWK_ + j)) * (2 * INNER) + h * DHEAD);
        float4 kk4 = kv[f];
        float4 vv4 = kv[96 + f];            // +INNER floats = 96 float4
        *reinterpret_cast<float4*>(K_s + j * KP + f * 4) = kk4;
        *reinterpret_cast<float4*>(V_s + j * 64 + f * 4) = vv4;
    }
    __syncthreads();

    const int w = tid >> 5;
    const int lane = tid & 31;
    float* qw = q_s + w * 512;
    float* pw = p_s + w * 2048;

    for (int it = 0; it < 4; ++it) {
        const int qg = qc * 256 + (it * 8 + w) * 8;  // base of 8 queries

        // cooperative load of 8 q vectors (8 x 16 float4)
        const float* qbase = g_Q + ((size_t)(b * HW_ + qg)) * INNER + h * DHEAD;
#pragma unroll
        for (int r = 0; r < 4; ++r) {
            int idx = r * 32 + lane;
            int qn = idx >> 4, f = idx & 15;
            *reinterpret_cast<float4*>(qw + qn * 64 + f * 4) =
                *reinterpret_cast<const float4*>(qbase + (size_t)qn * INNER + f * 4);
        }
        __syncwarp();

        // ---- QK^T: lane owns keys j = jj*32+lane; f32x2 over d-pairs ----
        u64 s2[8][8];
#pragma unroll
        for (int qn = 0; qn < 8; ++qn)
#pragma unroll
            for (int jj = 0; jj < 8; ++jj) s2[qn][jj] = 0ull;

#pragma unroll 4
        for (int dq = 0; dq < 16; ++dq) {
            u64 ql[8], qh[8];
#pragma unroll
            for (int qn = 0; qn < 8; ++qn) {
                ulonglong2 qv = *reinterpret_cast<const ulonglong2*>(qw + qn * 64 + dq * 4);
                ql[qn] = qv.x; qh[qn] = qv.y;
            }
#pragma unroll
            for (int jj = 0; jj < 8; ++jj) {
                ulonglong2 kv2 = *reinterpret_cast<const ulonglong2*>(
                    K_s + (size_t)(jj * 32 + lane) * KP + dq * 4);
#pragma unroll
                for (int qn = 0; qn < 8; ++qn) {
                    ffma2(s2[qn][jj], ql[qn], kv2.x);
                    ffma2(s2[qn][jj], qh[qn], kv2.y);
                }
            }
        }

        // ---- softmax (exact; p stored interleaved by q-pair) ----
        float linv[8];
#pragma unroll
        for (int qn = 0; qn < 8; ++qn) {
            float s[8];
            float m = -1e30f;
#pragma unroll
            for (int jj = 0; jj < 8; ++jj) {
                float2 f2 = unpack2(s2[qn][jj]);
                s[jj] = (f2.x + f2.y) * SCALE;
                m = fmaxf(m, s[jj]);
            }
#pragma unroll
            for (int o = 16; o > 0; o >>= 1)
                m = fmaxf(m, __shfl_xor_sync(0xffffffffu, m, o));
            float l = 0.f;
            float* pq = pw + (qn >> 1) * 512 + (qn & 1);
#pragma unroll
            for (int jj = 0; jj < 8; ++jj) {
                float p = __expf(s[jj] - m);
                pq[(jj * 32 + lane) * 2] = p;
                l += p;
            }
#pragma unroll
            for (int o = 16; o > 0; o >>= 1)
                l += __shfl_xor_sync(0xffffffffu, l, o);
            linv[qn] = 1.0f / l;
        }
        __syncwarp();

        // ---- P @ V : lane owns dims {2*lane, 2*lane+1}; f32x2 over q-pairs ----
        u64 acc2[4][2];
#pragma unroll
        for (int qp = 0; qp < 4; ++qp) { acc2[qp][0] = 0ull; acc2[qp][1] = 0ull; }

#pragma unroll 4
        for (int j2 = 0; j2 < 128; ++j2) {
            int j = j2 * 2;
            float2 va = *reinterpret_cast<const float2*>(V_s + (size_t)j * 64 + 2 * lane);
            float2 vb = *reinterpret_cast<const float2*>(V_s + (size_t)(j + 1) * 64 + 2 * lane);
            u64 va0 = pack2(va.x, va.x), va1 = pack2(va.y, va.y);
            u64 vb0 = pack2(vb.x, vb.x), vb1 = pack2(vb.y, vb.y);
#pragma unroll
            for (int qp = 0; qp < 4; ++qp) {
                ulonglong2 pv = *reinterpret_cast<const ulonglong2*>(pw + qp * 512 + j * 2);
                ffma2(acc2[qp][0], pv.x, va0);
                ffma2(acc2[qp][1], pv.x, va1);
                ffma2(acc2[qp][0], pv.y, vb0);
                ffma2(acc2[qp][1], pv.y, vb1);
            }
        }

#pragma unroll
        for (int qn = 0; qn < 8; ++qn) {
            int qp = qn >> 1, par = qn & 1;
            float2 f0 = unpack2(acc2[qp][0]);
            float2 f1 = unpack2(acc2[qp][1]);
            float o0 = (par ? f0.y : f0.x) * linv[qn];
            float o1 = (par ? f1.y : f1.x) * linv[qn];
            float2 ov = make_float2(o0, o1);
            *reinterpret_cast<float2*>(
                g_O + ((size_t)(b * HW_ + qg + qn)) * INNER + h * DHEAD + 2 * lane) = ov;
        }
        __syncwarp();
    }
}

// ---------------------------------------------------------------------------
// launcher
// ---------------------------------------------------------------------------
extern "C" void kernel_launch(void* const* d_in, const int* in_sizes, int n_in,
                              void* d_out, int out_size)
{
    (void)in_sizes; (void)n_in; (void)out_size;

    const float* x        = (const float*)d_in[0];
    const float* q_dw     = (const float*)d_in[1];
    const float* q_gamma  = (const float*)d_in[2];
    const float* q_beta   = (const float*)d_in[3];
    const float* q_mean   = (const float*)d_in[4];
    const float* q_var    = (const float*)d_in[5];
    const float* q_pw     = (const float*)d_in[6];
    const float* kv_dw    = (const float*)d_in[7];
    const float* kv_gamma = (const float*)d_in[8];
    const float* kv_beta  = (const float*)d_in[9];
    const float* kv_mean  = (const float*)d_in[10];
    const float* kv_var   = (const float*)d_in[11];
    const float* kv_pw    = (const float*)d_in[12];
    const float* out_w    = (const float*)d_in[13];
    const float* out_b    = (const float*)d_in[14];
    float* out = (float*)d_out;

    void *p_yq, *p_ykv, *p_Q, *p_KV, *p_O;
    cudaGetSymbolAddress(&p_yq,  g_yq);
    cudaGetSymbolAddress(&p_ykv, g_ykv);
    cudaGetSymbolAddress(&p_Q,   g_Q);
    cudaGetSymbolAddress(&p_KV,  g_KV);
    cudaGetSymbolAddress(&p_O,   g_O);

    // 1) depthwise conv + BN (both paths)
    dwbn_kernel<<<dim3(C_, B_), 256>>>(x,
        q_dw, q_gamma, q_beta, q_mean, q_var,
        kv_dw, kv_gamma, kv_beta, kv_mean, kv_var);

    // 2) Q pointwise:  [32768, 384] = yq(K-major) x q_pw
    gemm_pw<true, false><<<dim3((B_ * HW_) / 128, INNER / 128), 256>>>(
        (const float*)p_yq, q_pw, (float*)p_Q, nullptr, C_, INNER, HW_);

    // 3) KV pointwise: [8192, 768] = ykv(K-major) x kv_pw
    gemm_pw<true, false><<<dim3((B_ * HWK_) / 128, (2 * INNER) / 128), 256>>>(
        (const float*)p_ykv, kv_pw, (float*)p_KV, nullptr, C_, 2 * INNER, HWK_);

    // 4) attention
    cudaFuncSetAttribute(attn_kernel,
                         cudaFuncAttributeMaxDynamicSharedMemorySize,
                         ATTN_SMEM_BYTES);
    attn_kernel<<<dim3(4, HEADS, B_), 256, ATTN_SMEM_BYTES>>>();

    // 5) output projection -> NCHW with bias
    gemm_pw<false, true><<<dim3((B_ * HW_) / 128, C_ / 128), 256>>>(
        (const float*)p_O, out_w, out, out_b, INNER, C_, HW_);
}

// round 11
// speedup vs baseline: 1.2958x; 1.0832x over previous
#include <cuda_runtime.h>
#include <cuda_bf16.h>
#include <cstdint>
#include <cstddef>

// Problem constants
#define B_    32
#define C_    384
#define H_    32
#define W_    32
#define HW_   1024
#define HK_   16
#define WK_   16
#define HWK_  256
#define HEADS 6
#define DHEAD 64
#define INNER 384          // HEADS*DHEAD
#define SCALE 0.125f       // DIM_HEAD^-0.5
#define BN_EPS 1e-5f

typedef unsigned long long u64;

// ---------------------------------------------------------------------------
// f32x2 packed-FMA helpers (Blackwell FFMA2 — only reachable via PTX)
// ---------------------------------------------------------------------------
__device__ __forceinline__ void ffma2(u64 &c, u64 a, u64 b) {
    asm("fma.rn.f32x2 %0, %1, %2, %0;" : "+l"(c) : "l"(a), "l"(b));
}
__device__ __forceinline__ u64 pack2(float lo, float hi) {
    u64 r; asm("mov.b64 %0, {%1, %2};" : "=l"(r) : "f"(lo), "f"(hi)); return r;
}
__device__ __forceinline__ float2 unpack2(u64 v) {
    float2 f; asm("mov.b64 {%0, %1}, %2;" : "=f"(f.x), "=f"(f.y) : "l"(v)); return f;
}
__device__ __forceinline__ u64 mul2(u64 a, u64 b) {
    u64 r; asm("mul.rn.f32x2 %0, %1, %2;" : "=l"(r) : "l"(a), "l"(b)); return r;
}

// ---------------------------------------------------------------------------
// Scratch (static device globals; no runtime allocation allowed)
// ---------------------------------------------------------------------------
__device__ float g_yq [(size_t)B_ * C_ * HW_];    // dw+bn output, Q path   [b][c][pix]
__device__ float g_ykv[(size_t)B_ * C_ * HWK_];   // dw+bn output, KV path  [b][c][pix]
__device__ float g_Q  [(size_t)B_ * HW_ * INNER]; // Q projection  [n][384]
__device__ float g_KV [(size_t)B_ * HWK_ * 2 * INNER]; // KV projection [n][768]
__device__ float g_O  [(size_t)B_ * HW_ * INNER]; // attention out [n][384]

// ---------------------------------------------------------------------------
// Kernel 1: fused depthwise 3x3 (+BN) for BOTH Q (stride 1) and KV (stride 2)
// One block per (b, c) plane. Plane staged in smem once.
// ---------------------------------------------------------------------------
__global__ __launch_bounds__(256)
void dwbn_kernel(const float* __restrict__ x,
                 const float* __restrict__ q_dw,  const float* __restrict__ q_gamma,
                 const float* __restrict__ q_beta, const float* __restrict__ q_mean,
                 const float* __restrict__ q_var,
                 const float* __restrict__ kv_dw, const float* __restrict__ kv_gamma,
                 const float* __restrict__ kv_beta, const float* __restrict__ kv_mean,
                 const float* __restrict__ kv_var)
{
    const int c = blockIdx.x;
    const int b = blockIdx.y;
    const int tid = threadIdx.x;

    __shared__ float sx[34 * 34];

    const float* xp = x + ((size_t)b * C_ + c) * HW_;

    for (int i = tid; i < 34 * 34; i += 256) {
        int r = i / 34, cc = i % 34;
        int iy = r - 1, ix = cc - 1;
        float v = 0.f;
        if (iy >= 0 && iy < 32 && ix >= 0 && ix < 32) v = xp[iy * 32 + ix];
        sx[i] = v;
    }
    __syncthreads();

    float wq[9], wk[9];
#pragma unroll
    for (int i = 0; i < 9; ++i) { wq[i] = q_dw[c * 9 + i]; wk[i] = kv_dw[c * 9 + i]; }
    const float invq = q_gamma[c] * rsqrtf(q_var[c] + BN_EPS);
    const float addq = q_beta[c] - q_mean[c] * invq;
    const float invk = kv_gamma[c] * rsqrtf(kv_var[c] + BN_EPS);
    const float addk = kv_beta[c] - kv_mean[c] * invk;

    float* yq = g_yq + ((size_t)b * C_ + c) * HW_;
#pragma unroll
    for (int p = tid; p < HW_; p += 256) {
        int oy = p >> 5, ox = p & 31;
        float s = 0.f;
#pragma unroll
        for (int r = 0; r < 3; ++r)
#pragma unroll
            for (int ss = 0; ss < 3; ++ss)
                s += wq[r * 3 + ss] * sx[(oy + r) * 34 + ox + ss];
        yq[p] = s * invq + addq;
    }

    float* yk = g_ykv + ((size_t)b * C_ + c) * HWK_;
    if (tid < HWK_) {
        int oy = tid >> 4, ox = tid & 15;
        float s = 0.f;
#pragma unroll
        for (int r = 0; r < 3; ++r)
#pragma unroll
            for (int ss = 0; ss < 3; ++ss)
                s += wk[r * 3 + ss] * sx[(2 * oy + r) * 34 + 2 * ox + ss];
        yk[tid] = s * invk + addk;
    }
}

// ---------------------------------------------------------------------------
// Kernel 2: pointwise-conv GEMM, FFMA2, double-buffered, dup-j operand.
//   Cout(n, m) = sum_k A(k|n) * W(m, k)
//   <true,false>  (Q,KV): A K-major per batch; out row-major. i-axis = n (plain),
//                 j-axis = m (W duplicated in smem as u64).
//   <false,true>  (Out):  A row-major; out channel-major NCHW + bias. i-axis = m
//                 (W plain), j-axis = n (A duplicated).
// Tile 128x128, k-chunk 8, 256 threads.
// Thread (w, lane): it = lane&15, jt2 = lane>>4.
//   i rows: {it*4 .. it*4+3} and {64+it*4 .. +3}   (conflict-free pair LDS)
//   j cols: w*16 + jt2*8 .. +7                      (warp-broadcast LDS)
// ---------------------------------------------------------------------------
template <bool AKM, bool CCM>
__global__ __launch_bounds__(256, 2)
void gemm_pw(const float* __restrict__ A, const float* __restrict__ W,
             float* __restrict__ Cout, const float* __restrict__ bias,
             int K, int M, int HWb)
{
    __shared__ float Ps[2][8][128];   // plain (i-axis) operand
    __shared__ u64   Ds[2][8][128];   // duplicated (j-axis) operand

    const int tid  = threadIdx.x;
    const int w    = tid >> 5;
    const int lane = tid & 31;
    const int n0 = blockIdx.x * 128;
    const int m0 = blockIdx.y * 128;
    const int it  = lane & 15;
    const int j0t = w * 16 + (lane >> 4) * 8;

    const float* Ab = A;
    if (AKM) {
        int batch = n0 / HWb;
        Ab = A + (size_t)batch * K * HWb + (n0 % HWb);
    }

    // staging lane assignments
    const int pk = tid >> 5;           // AKM plain: k row (0..7)
    const int pn = (tid & 31) << 2;    // AKM plain: n col (x4)
    const int rm = tid >> 1;           // row-major row (0..127)
    const int rk = (tid & 1) << 2;     // row-major k offset (0 or 4)

    u64 acc2[4][8];
#pragma unroll
    for (int i = 0; i < 4; ++i)
#pragma unroll
        for (int j = 0; j < 8; ++j) acc2[i][j] = 0ull;

    float4 fP, fD;
    // global chunk load
    {
        if (AKM) {
            fP = *reinterpret_cast<const float4*>(Ab + (size_t)pk * HWb + pn);
            fD = *reinterpret_cast<const float4*>(W + (size_t)(m0 + rm) * K + rk);
        } else {
            fP = *reinterpret_cast<const float4*>(W + (size_t)(m0 + rm) * K + rk);
            fD = *reinterpret_cast<const float4*>(A + (size_t)(n0 + rm) * K + rk);
        }
    }
    // store chunk 0
    {
        if (AKM) {
            *reinterpret_cast<float4*>(&Ps[0][pk][pn]) = fP;
        } else {
            Ps[0][rk + 0][rm] = fP.x; Ps[0][rk + 1][rm] = fP.y;
            Ps[0][rk + 2][rm] = fP.z; Ps[0][rk + 3][rm] = fP.w;
        }
        Ds[0][rk + 0][rm] = pack2(fD.x, fD.x);
        Ds[0][rk + 1][rm] = pack2(fD.y, fD.y);
        Ds[0][rk + 2][rm] = pack2(fD.z, fD.z);
        Ds[0][rk + 3][rm] = pack2(fD.w, fD.w);
    }
    __syncthreads();

    int buf = 0;
    for (int k0 = 0; k0 < K; k0 += 8) {
        const bool nxt = (k0 + 8) < K;
        float4 nP, nD;
        if (nxt) {
            int kn = k0 + 8;
            if (AKM) {
                nP = *reinterpret_cast<const float4*>(Ab + (size_t)(kn + pk) * HWb + pn);
                nD = *reinterpret_cast<const float4*>(W + (size_t)(m0 + rm) * K + kn + rk);
            } else {
                nP = *reinterpret_cast<const float4*>(W + (size_t)(m0 + rm) * K + kn + rk);
                nD = *reinterpret_cast<const float4*>(A + (size_t)(n0 + rm) * K + kn + rk);
            }
        }

#pragma unroll
        for (int kk = 0; kk < 8; ++kk) {
            ulonglong2 aA = *reinterpret_cast<const ulonglong2*>(&Ps[buf][kk][it * 4]);
            ulonglong2 aB = *reinterpret_cast<const ulonglong2*>(&Ps[buf][kk][64 + it * 4]);
            const u64* dr = &Ds[buf][kk][j0t];
            ulonglong2 d0 = *reinterpret_cast<const ulonglong2*>(dr);
            ulonglong2 d1 = *reinterpret_cast<const ulonglong2*>(dr + 2);
            ulonglong2 d2 = *reinterpret_cast<const ulonglong2*>(dr + 4);
            ulonglong2 d3 = *reinterpret_cast<const ulonglong2*>(dr + 6);
            u64 bd[8] = { d0.x, d0.y, d1.x, d1.y, d2.x, d2.y, d3.x, d3.y };
#pragma unroll
            for (int j = 0; j < 8; ++j) {
                ffma2(acc2[0][j], aA.x, bd[j]);
                ffma2(acc2[1][j], aA.y, bd[j]);
                ffma2(acc2[2][j], aB.x, bd[j]);
                ffma2(acc2[3][j], aB.y, bd[j]);
            }
        }

        if (nxt) {
            int nb = buf ^ 1;
            if (AKM) {
                *reinterpret_cast<float4*>(&Ps[nb][pk][pn]) = nP;
            } else {
                Ps[nb][rk + 0][rm] = nP.x; Ps[nb][rk + 1][rm] = nP.y;
                Ps[nb][rk + 2][rm] = nP.z; Ps[nb][rk + 3][rm] = nP.w;
            }
            Ds[nb][rk + 0][rm] = pack2(nD.x, nD.x);
            Ds[nb][rk + 1][rm] = pack2(nD.y, nD.y);
            Ds[nb][rk + 2][rm] = pack2(nD.z, nD.z);
            Ds[nb][rk + 3][rm] = pack2(nD.w, nD.w);
            __syncthreads();
        }
        buf ^= 1;
    }

    // Epilogue. Local row r = g*64 + it*4 + p2*2 + e  (g: group, p2: pair, e: elem)
#pragma unroll
    for (int g = 0; g < 2; ++g) {
#pragma unroll
        for (int p2 = 0; p2 < 2; ++p2) {
            float v0[8], v1[8];
#pragma unroll
            for (int j = 0; j < 8; ++j) {
                float2 f = unpack2(acc2[g * 2 + p2][j]);
                v0[j] = f.x; v1[j] = f.y;
            }
            int rl = g * 64 + it * 4 + p2 * 2;
            if (!CCM) {
                size_t r0 = (size_t)(n0 + rl) * M + m0 + j0t;
                size_t r1 = (size_t)(n0 + rl + 1) * M + m0 + j0t;
                *reinterpret_cast<float4*>(Cout + r0)     = make_float4(v0[0], v0[1], v0[2], v0[3]);
                *reinterpret_cast<float4*>(Cout + r0 + 4) = make_float4(v0[4], v0[5], v0[6], v0[7]);
                *reinterpret_cast<float4*>(Cout + r1)     = make_float4(v1[0], v1[1], v1[2], v1[3]);
                *reinterpret_cast<float4*>(Cout + r1 + 4) = make_float4(v1[4], v1[5], v1[6], v1[7]);
            } else {
                int batch = n0 / HWb;
                int pix0  = (n0 % HWb) + j0t;
                int ch0 = m0 + rl;
                float b0 = bias ? bias[ch0] : 0.f;
                float b1 = bias ? bias[ch0 + 1] : 0.f;
                size_t r0 = ((size_t)batch * M + ch0) * HWb + pix0;
                size_t r1 = ((size_t)batch * M + ch0 + 1) * HWb + pix0;
                *reinterpret_cast<float4*>(Cout + r0)     = make_float4(v0[0]+b0, v0[1]+b0, v0[2]+b0, v0[3]+b0);
                *reinterpret_cast<float4*>(Cout + r0 + 4) = make_float4(v0[4]+b0, v0[5]+b0, v0[6]+b0, v0[7]+b0);
                *reinterpret_cast<float4*>(Cout + r1)     = make_float4(v1[0]+b1, v1[1]+b1, v1[2]+b1, v1[3]+b1);
                *reinterpret_cast<float4*>(Cout + r1 + 4) = make_float4(v1[4]+b1, v1[5]+b1, v1[6]+b1, v1[7]+b1);
            }
        }
    }
}

// ---------------------------------------------------------------------------
// Kernel 3: attention, two-phase flash over key halves (occ 2 CTA/SM).
// grid (qchunk=16, head=6, batch=32), 256 threads (8 warps), each warp: 8 q.
// smem: K_s [128][68] | V_s [128][64] | qp 8w x 1024 (q first 512, then p [qp][j][2])
// Phase h stages keys h*128..h*128+127; exact flash rescale between phases.
// ---------------------------------------------------------------------------
#define KP 68
#define ATTN_SMEM_FLOATS (128 * KP + 128 * 64 + 8 * 1024)
#define ATTN_SMEM_BYTES  (ATTN_SMEM_FLOATS * 4)

__global__ __launch_bounds__(256, 2)
void attn_kernel()
{
    extern __shared__ float sm[];
    float* K_s  = sm;                    // [128][KP]
    float* V_s  = sm + 128 * KP;         // [128][64]
    float* qp_s = V_s + 128 * 64;        // per warp 1024 floats

    const int qc = blockIdx.x;   // 0..15
    const int h  = blockIdx.y;   // 0..5
    const int b  = blockIdx.z;   // 0..31
    const int tid  = threadIdx.x;
    const int w    = tid >> 5;
    const int lane = tid & 31;
    float* qw = qp_s + (w << 10);
    const int qg = qc * 64 + w * 8;

    float mq[8], lq[8];
    u64 acc2[4][2];
#pragma unroll
    for (int qp = 0; qp < 4; ++qp) { acc2[qp][0] = 0ull; acc2[qp][1] = 0ull; }

    for (int half = 0; half < 2; ++half) {
        __syncthreads();   // all warps done with previous phase's K_s/V_s reads
        for (int idx = tid; idx < 128 * 16; idx += 256) {
            int j = idx >> 4, f = idx & 15;
            const float4* kv = reinterpret_cast<const float4*>(
                g_KV + ((size_t)(b * HWK_ + half * 128 + j)) * (2 * INNER) + h * DHEAD);
            *reinterpret_cast<float4*>(K_s + j * KP + f * 4) = kv[f];
            *reinterpret_cast<float4*>(V_s + j * 64 + f * 4) = kv[96 + f];
        }
        __syncthreads();

        // (re)load q into qw[0..511]
        const float* qbase = g_Q + ((size_t)(b * HW_ + qg)) * INNER + h * DHEAD;
#pragma unroll
        for (int r = 0; r < 4; ++r) {
            int idx = r * 32 + lane;
            int qn = idx >> 4, f = idx & 15;
            *reinterpret_cast<float4*>(qw + qn * 64 + f * 4) =
                *reinterpret_cast<const float4*>(qbase + (size_t)qn * INNER + f * 4);
        }
        __syncwarp();

        // ---- QK^T over this half: lane owns keys jj*32+lane (jj 0..3) ----
        u64 s2[8][4];
#pragma unroll
        for (int qn = 0; qn < 8; ++qn)
#pragma unroll
            for (int jj = 0; jj < 4; ++jj) s2[qn][jj] = 0ull;

#pragma unroll 4
        for (int dq = 0; dq < 16; ++dq) {
            ulonglong2 kv2[4];
#pragma unroll
            for (int jj = 0; jj < 4; ++jj)
                kv2[jj] = *reinterpret_cast<const ulonglong2*>(
                    K_s + (size_t)(jj * 32 + lane) * KP + dq * 4);
#pragma unroll
            for (int g = 0; g < 2; ++g) {
                u64 ql[4], qh[4];
#pragma unroll
                for (int q4 = 0; q4 < 4; ++q4) {
                    ulonglong2 qv = *reinterpret_cast<const ulonglong2*>(
                        qw + (g * 4 + q4) * 64 + dq * 4);
                    ql[q4] = qv.x; qh[q4] = qv.y;
                }
#pragma unroll
                for (int jj = 0; jj < 4; ++jj)
#pragma unroll
                    for (int q4 = 0; q4 < 4; ++q4) {
                        ffma2(s2[g * 4 + q4][jj], ql[q4], kv2[jj].x);
                        ffma2(s2[g * 4 + q4][jj], qh[q4], kv2[jj].y);
                    }
            }
        }
        __syncwarp();   // q reads done; qw may be overwritten with p

        // ---- partial softmax + flash merge ----
        float resc[8];
#pragma unroll
        for (int qn = 0; qn < 8; ++qn) {
            float s[4];
            float ml = -1e30f;
#pragma unroll
            for (int jj = 0; jj < 4; ++jj) {
                float2 f2 = unpack2(s2[qn][jj]);
                s[jj] = (f2.x + f2.y) * SCALE;
                ml = fmaxf(ml, s[jj]);
            }
#pragma unroll
            for (int o = 16; o > 0; o >>= 1)
                ml = fmaxf(ml, __shfl_xor_sync(0xffffffffu, ml, o));
            float mnew = (half == 0) ? ml : fmaxf(mq[qn], ml);
            float r    = (half == 0) ? 0.f : __expf(mq[qn] - mnew);
            float l = 0.f;
            float* pq = qw + (qn >> 1) * 256 + (qn & 1);
#pragma unroll
            for (int jj = 0; jj < 4; ++jj) {
                float p = __expf(s[jj] - mnew);
                pq[(jj * 32 + lane) * 2] = p;
                l += p;
            }
#pragma unroll
            for (int o = 16; o > 0; o >>= 1)
                l += __shfl_xor_sync(0xffffffffu, l, o);
            lq[qn] = (half == 0) ? l : lq[qn] * r + l;
            mq[qn] = mnew;
            resc[qn] = r;
        }
        __syncwarp();

        if (half == 1) {
#pragma unroll
            for (int qp = 0; qp < 4; ++qp) {
                u64 rr = pack2(resc[2 * qp], resc[2 * qp + 1]);
                acc2[qp][0] = mul2(acc2[qp][0], rr);
                acc2[qp][1] = mul2(acc2[qp][1], rr);
            }
        }

        // ---- P @ V over this half: lane owns dims {2lane, 2lane+1} ----
#pragma unroll 4
        for (int j2 = 0; j2 < 64; ++j2) {
            int j = j2 * 2;
            float2 va = *reinterpret_cast<const float2*>(V_s + (size_t)j * 64 + 2 * lane);
            float2 vb = *reinterpret_cast<const float2*>(V_s + (size_t)(j + 1) * 64 + 2 * lane);
            u64 va0 = pack2(va.x, va.x), va1 = pack2(va.y, va.y);
            u64 vb0 = pack2(vb.x, vb.x), vb1 = pack2(vb.y, vb.y);
#pragma unroll
            for (int qp = 0; qp < 4; ++qp) {
                ulonglong2 pv = *reinterpret_cast<const ulonglong2*>(qw + qp * 256 + j * 2);
                ffma2(acc2[qp][0], pv.x, va0);
                ffma2(acc2[qp][1], pv.x, va1);
                ffma2(acc2[qp][0], pv.y, vb0);
                ffma2(acc2[qp][1], pv.y, vb1);
            }
        }
    }

    // ---- write out ----
#pragma unroll
    for (int qn = 0; qn < 8; ++qn) {
        int qp = qn >> 1, par = qn & 1;
        float2 f0 = unpack2(acc2[qp][0]);
        float2 f1 = unpack2(acc2[qp][1]);
        float linv = 1.0f / lq[qn];
        float o0 = (par ? f0.y : f0.x) * linv;
        float o1 = (par ? f1.y : f1.x) * linv;
        *reinterpret_cast<float2*>(
            g_O + ((size_t)(b * HW_ + qg + qn)) * INNER + h * DHEAD + 2 * lane) =
            make_float2(o0, o1);
    }
}

// ---------------------------------------------------------------------------
// launcher
// ---------------------------------------------------------------------------
extern "C" void kernel_launch(void* const* d_in, const int* in_sizes, int n_in,
                              void* d_out, int out_size)
{
    (void)in_sizes; (void)n_in; (void)out_size;

    const float* x        = (const float*)d_in[0];
    const float* q_dw     = (const float*)d_in[1];
    const float* q_gamma  = (const float*)d_in[2];
    const float* q_beta   = (const float*)d_in[3];
    const float* q_mean   = (const float*)d_in[4];
    const float* q_var    = (const float*)d_in[5];
    const float* q_pw     = (const float*)d_in[6];
    const float* kv_dw    = (const float*)d_in[7];
    const float* kv_gamma = (const float*)d_in[8];
    const float* kv_beta  = (const float*)d_in[9];
    const float* kv_mean  = (const float*)d_in[10];
    const float* kv_var   = (const float*)d_in[11];
    const float* kv_pw    = (const float*)d_in[12];
    const float* out_w    = (const float*)d_in[13];
    const float* out_b    = (const float*)d_in[14];
    float* out = (float*)d_out;

    void *p_yq, *p_ykv, *p_Q, *p_KV, *p_O;
    cudaGetSymbolAddress(&p_yq,  g_yq);
    cudaGetSymbolAddress(&p_ykv, g_ykv);
    cudaGetSymbolAddress(&p_Q,   g_Q);
    cudaGetSymbolAddress(&p_KV,  g_KV);
    cudaGetSymbolAddress(&p_O,   g_O);

    // 1) depthwise conv + BN (both paths)
    dwbn_kernel<<<dim3(C_, B_), 256>>>(x,
        q_dw, q_gamma, q_beta, q_mean, q_var,
        kv_dw, kv_gamma, kv_beta, kv_mean, kv_var);

    // 2) Q pointwise:  [32768, 384] = yq(K-major) x q_pw   -> row-major g_Q
    gemm_pw<true, false><<<dim3((B_ * HW_) / 128, INNER / 128), 256>>>(
        (const float*)p_yq, q_pw, (float*)p_Q, nullptr, C_, INNER, HW_);

    // 3) KV pointwise: [8192, 768] = ykv(K-major) x kv_pw  -> row-major g_KV
    gemm_pw<true, false><<<dim3((B_ * HWK_) / 128, (2 * INNER) / 128), 256>>>(
        (const float*)p_ykv, kv_pw, (float*)p_KV, nullptr, C_, 2 * INNER, HWK_);

    // 4) attention (two-phase flash, occ 2)
    cudaFuncSetAttribute(attn_kernel,
                         cudaFuncAttributeMaxDynamicSharedMemorySize,
                         ATTN_SMEM_BYTES);
    attn_kernel<<<dim3(16, HEADS, B_), 256, ATTN_SMEM_BYTES>>>();

    // 5) output projection -> NCHW with bias
    gemm_pw<false, true><<<dim3((B_ * HW_) / 128, C_ / 128), 256>>>(
        (const float*)p_O, out_w, out, out_b, INNER, C_, HW_);
}

// round 12
// speedup vs baseline: 1.6264x; 1.2551x over previous
#include <cuda_runtime.h>
#include <cuda_bf16.h>
#include <cstdint>
#include <cstddef>

// Problem constants
#define B_    32
#define C_    384
#define H_    32
#define W_    32
#define HW_   1024
#define HK_   16
#define WK_   16
#define HWK_  256
#define HEADS 6
#define DHEAD 64
#define INNER 384          // HEADS*DHEAD
#define SCALE 0.125f       // DIM_HEAD^-0.5
#define BN_EPS 1e-5f

typedef unsigned long long u64;

// ---------------------------------------------------------------------------
// f32x2 packed-FMA helpers (attention kernel)
// ---------------------------------------------------------------------------
__device__ __forceinline__ void ffma2(u64 &c, u64 a, u64 b) {
    asm("fma.rn.f32x2 %0, %1, %2, %0;" : "+l"(c) : "l"(a), "l"(b));
}
__device__ __forceinline__ u64 pack2(float lo, float hi) {
    u64 r; asm("mov.b64 %0, {%1, %2};" : "=l"(r) : "f"(lo), "f"(hi)); return r;
}
__device__ __forceinline__ float2 unpack2(u64 v) {
    float2 f; asm("mov.b64 {%0, %1}, %2;" : "=f"(f.x), "=f"(f.y) : "l"(v)); return f;
}
__device__ __forceinline__ u64 mul2(u64 a, u64 b) {
    u64 r; asm("mul.rn.f32x2 %0, %1, %2;" : "=l"(r) : "l"(a), "l"(b)); return r;
}

// tf32 helpers (tensor-core GEMM)
__device__ __forceinline__ float to_tf32f(float x) {
    uint32_t r; asm("cvt.rna.tf32.f32 %0, %1;" : "=r"(r) : "f"(x));
    return __uint_as_float(r);
}
__device__ __forceinline__ void mma_tf32(float* d, const uint32_t* a, const uint32_t* b) {
    asm volatile(
        "mma.sync.aligned.m16n8k8.row.col.f32.tf32.tf32.f32 "
        "{%0,%1,%2,%3}, {%4,%5,%6,%7}, {%8,%9}, {%0,%1,%2,%3};"
        : "+f"(d[0]), "+f"(d[1]), "+f"(d[2]), "+f"(d[3])
        : "r"(a[0]), "r"(a[1]), "r"(a[2]), "r"(a[3]), "r"(b[0]), "r"(b[1]));
}

// ---------------------------------------------------------------------------
// Scratch (static device globals; no runtime allocation allowed)
// ---------------------------------------------------------------------------
__device__ float g_yq [(size_t)B_ * HW_ * C_];          // dw+bn out, Q path [b*1024+pix][c]
__device__ float g_ykv[(size_t)B_ * HWK_ * C_];         // dw+bn out, KV path [b*256+pix][c]
__device__ float g_Q  [(size_t)B_ * HW_ * INNER];       // Q row-major [n][384]
__device__ float g_KV [(size_t)B_ * HWK_ * 2 * INNER];  // KV row-major [n][768]
__device__ float g_O  [(size_t)B_ * HW_ * INNER];       // attention out row-major [n][384]

// ---------------------------------------------------------------------------
// Kernel 1: fused depthwise 3x3 (+BN), 8-channel groups, TRANSPOSED outputs.
// grid (48 cgroups, 32 batch), 256 threads. Writes y[pix][c0..c0+7].
// ---------------------------------------------------------------------------
__global__ __launch_bounds__(256)
void dwbn_kernel(const float* __restrict__ x,
                 const float* __restrict__ q_dw,  const float* __restrict__ q_gamma,
                 const float* __restrict__ q_beta, const float* __restrict__ q_mean,
                 const float* __restrict__ q_var,
                 const float* __restrict__ kv_dw, const float* __restrict__ kv_gamma,
                 const float* __restrict__ kv_beta, const float* __restrict__ kv_mean,
                 const float* __restrict__ kv_var)
{
    const int g  = blockIdx.x;     // channel group (8 ch)
    const int b  = blockIdx.y;
    const int c0 = g * 8;
    const int tid = threadIdx.x;

    __shared__ float sx[8][34 * 34];
    __shared__ float wq_s[72], wk_s[72];
    __shared__ float bn_s[32];   // invq[8] addq[8] invk[8] addk[8]

    for (int idx = tid; idx < 8 * 1156; idx += 256) {
        int cc = idx / 1156, i = idx - cc * 1156;
        int r = i / 34, col = i - r * 34;
        int iy = r - 1, ix = col - 1;
        float v = 0.f;
        if (iy >= 0 && iy < 32 && ix >= 0 && ix < 32)
            v = x[((size_t)b * C_ + c0 + cc) * HW_ + iy * 32 + ix];
        sx[cc][i] = v;
    }
    if (tid < 72) { wq_s[tid] = q_dw[c0 * 9 + tid]; wk_s[tid] = kv_dw[c0 * 9 + tid]; }
    if (tid < 8) {
        int c = c0 + tid;
        float iq = q_gamma[c] * rsqrtf(q_var[c] + BN_EPS);
        bn_s[tid]      = iq;
        bn_s[8 + tid]  = q_beta[c] - q_mean[c] * iq;
        float ik = kv_gamma[c] * rsqrtf(kv_var[c] + BN_EPS);
        bn_s[16 + tid] = ik;
        bn_s[24 + tid] = kv_beta[c] - kv_mean[c] * ik;
    }
    __syncthreads();

    // Q path (stride 1): transposed write y[pix][c0..c0+7]
    for (int p = tid; p < HW_; p += 256) {
        int oy = p >> 5, ox = p & 31;
        float o8[8];
#pragma unroll
        for (int cc = 0; cc < 8; ++cc) {
            const float* sp = &sx[cc][oy * 34 + ox];
            float s = 0.f;
#pragma unroll
            for (int r = 0; r < 3; ++r)
#pragma unroll
                for (int ss = 0; ss < 3; ++ss)
                    s += wq_s[cc * 9 + r * 3 + ss] * sp[r * 34 + ss];
            o8[cc] = s * bn_s[cc] + bn_s[8 + cc];
        }
        float4* dst = reinterpret_cast<float4*>(g_yq + ((size_t)b * HW_ + p) * C_ + c0);
        dst[0] = make_float4(o8[0], o8[1], o8[2], o8[3]);
        dst[1] = make_float4(o8[4], o8[5], o8[6], o8[7]);
    }

    // KV path (stride 2)
    if (tid < HWK_) {
        int oy = tid >> 4, ox = tid & 15;
        float o8[8];
#pragma unroll
        for (int cc = 0; cc < 8; ++cc) {
            const float* sp = &sx[cc][(2 * oy) * 34 + 2 * ox];
            float s = 0.f;
#pragma unroll
            for (int r = 0; r < 3; ++r)
#pragma unroll
                for (int ss = 0; ss < 3; ++ss)
                    s += wk_s[cc * 9 + r * 3 + ss] * sp[r * 34 + ss];
            o8[cc] = s * bn_s[16 + cc] + bn_s[24 + cc];
        }
        float4* dst = reinterpret_cast<float4*>(g_ykv + ((size_t)b * HWK_ + tid) * C_ + c0);
        dst[0] = make_float4(o8[0], o8[1], o8[2], o8[3]);
        dst[1] = make_float4(o8[4], o8[5], o8[6], o8[7]);
    }
}

// ---------------------------------------------------------------------------
// Kernel 2: tensor-core tf32 GEMM via mma.sync.m16n8k8.
//   D[m][n] = sum_k Amat[m][k] * Bmat[n][k],  K = 384 fixed, both row-major.
//   Tile 128x128, 8 warps each 64x32 (4 m-frags x 4 n-frags of 16x8).
//   smem: [op][buf][k8grp][row 128][10]  (8 data floats as (k,k+4) pairs + 2 pad)
//   k-chunk = 16 (2 k8 groups), double buffered, 24 chunks.
//   OUTMODE 0: row-major out [m][Nt];  blockIdx.x = n-tile, blockIdx.y = m-tile
//   OUTMODE 1: NCHW + bias: m = channel, n = global pixel;
//              blockIdx.x = m-tile, blockIdx.y = n-tile
// ---------------------------------------------------------------------------
template <int OUTMODE>
__global__ __launch_bounds__(256, 2)
void gemm_mma(const float* __restrict__ Amat, const float* __restrict__ Bmat,
              float* __restrict__ Cout, const float* __restrict__ bias, int Nt)
{
    __shared__ float smem[2][2][2][128][10];   // 40960 bytes

    const int tid  = threadIdx.x;
    const int lane = tid & 31;
    const int w    = tid >> 5;
    const int mw   = w & 1;          // m half (0/1) -> 64 rows
    const int nw   = w >> 1;         // n quarter (0..3) -> 32 cols
    const int qrow = lane >> 2;      // 0..7
    const int qk   = (lane & 3) * 2; // elem offset within row (pair index *2)

    int m0, n0;
    if (OUTMODE == 0) { n0 = blockIdx.x * 128; m0 = blockIdx.y * 128; }
    else              { m0 = blockIdx.x * 128; n0 = blockIdx.y * 128; }

    // staging: one row per thread; tid<128 -> A rows, else B rows
    const int srow = tid & 127;
    const int sop  = tid >> 7;
    const float* src = (sop == 0) ? (Amat + (size_t)(m0 + srow) * 384)
                                  : (Bmat + (size_t)(n0 + srow) * 384);

    float acc[4][4][4];
#pragma unroll
    for (int f = 0; f < 4; ++f)
#pragma unroll
        for (int j = 0; j < 4; ++j)
#pragma unroll
            for (int e = 0; e < 4; ++e) acc[f][j][e] = 0.f;

    float4 pf0, pf1, pf2, pf3;
    // load + store chunk 0
    {
        const float4* gsrc = reinterpret_cast<const float4*>(src);
        pf0 = gsrc[0]; pf1 = gsrc[1]; pf2 = gsrc[2]; pf3 = gsrc[3];
        float2* d0 = reinterpret_cast<float2*>(&smem[sop][0][0][srow][0]);
        float2* d1 = reinterpret_cast<float2*>(&smem[sop][0][1][srow][0]);
        d0[0] = make_float2(to_tf32f(pf0.x), to_tf32f(pf1.x));
        d0[1] = make_float2(to_tf32f(pf0.y), to_tf32f(pf1.y));
        d0[2] = make_float2(to_tf32f(pf0.z), to_tf32f(pf1.z));
        d0[3] = make_float2(to_tf32f(pf0.w), to_tf32f(pf1.w));
        d1[0] = make_float2(to_tf32f(pf2.x), to_tf32f(pf3.x));
        d1[1] = make_float2(to_tf32f(pf2.y), to_tf32f(pf3.y));
        d1[2] = make_float2(to_tf32f(pf2.z), to_tf32f(pf3.z));
        d1[3] = make_float2(to_tf32f(pf2.w), to_tf32f(pf3.w));
    }
    __syncthreads();

    int buf = 0;
    for (int c = 0; c < 24; ++c) {
        if (c + 1 < 24) {
            const float4* gsrc = reinterpret_cast<const float4*>(src + (c + 1) * 16);
            pf0 = gsrc[0]; pf1 = gsrc[1]; pf2 = gsrc[2]; pf3 = gsrc[3];
        }

#pragma unroll
        for (int grp = 0; grp < 2; ++grp) {
            uint32_t a[4][4];
#pragma unroll
            for (int f = 0; f < 4; ++f) {
                float2 lo = *reinterpret_cast<const float2*>(
                    &smem[0][buf][grp][mw * 64 + f * 16 + qrow][qk]);
                float2 hi = *reinterpret_cast<const float2*>(
                    &smem[0][buf][grp][mw * 64 + f * 16 + 8 + qrow][qk]);
                a[f][0] = __float_as_uint(lo.x);
                a[f][1] = __float_as_uint(hi.x);
                a[f][2] = __float_as_uint(lo.y);
                a[f][3] = __float_as_uint(hi.y);
            }
            uint32_t bf[4][2];
#pragma unroll
            for (int j = 0; j < 4; ++j) {
                float2 bb = *reinterpret_cast<const float2*>(
                    &smem[1][buf][grp][nw * 32 + j * 8 + qrow][qk]);
                bf[j][0] = __float_as_uint(bb.x);
                bf[j][1] = __float_as_uint(bb.y);
            }
#pragma unroll
            for (int f = 0; f < 4; ++f)
#pragma unroll
                for (int j = 0; j < 4; ++j)
                    mma_tf32(acc[f][j], a[f], bf[j]);
        }

        if (c + 1 < 24) {
            int nb = buf ^ 1;
            float2* d0 = reinterpret_cast<float2*>(&smem[sop][nb][0][srow][0]);
            float2* d1 = reinterpret_cast<float2*>(&smem[sop][nb][1][srow][0]);
            d0[0] = make_float2(to_tf32f(pf0.x), to_tf32f(pf1.x));
            d0[1] = make_float2(to_tf32f(pf0.y), to_tf32f(pf1.y));
            d0[2] = make_float2(to_tf32f(pf0.z), to_tf32f(pf1.z));
            d0[3] = make_float2(to_tf32f(pf0.w), to_tf32f(pf1.w));
            d1[0] = make_float2(to_tf32f(pf2.x), to_tf32f(pf3.x));
            d1[1] = make_float2(to_tf32f(pf2.y), to_tf32f(pf3.y));
            d1[2] = make_float2(to_tf32f(pf2.z), to_tf32f(pf3.z));
            d1[3] = make_float2(to_tf32f(pf2.w), to_tf32f(pf3.w));
            __syncthreads();
        }
        buf ^= 1;
    }

    // Epilogue
#pragma unroll
    for (int f = 0; f < 4; ++f) {
#pragma unroll
        for (int j = 0; j < 4; ++j) {
            int gm = m0 + mw * 64 + f * 16 + qrow;
            int gn = n0 + nw * 32 + j * 8 + (lane & 3) * 2;
            if (OUTMODE == 0) {
                *reinterpret_cast<float2*>(&Cout[(size_t)gm * Nt + gn]) =
                    make_float2(acc[f][j][0], acc[f][j][1]);
                *reinterpret_cast<float2*>(&Cout[(size_t)(gm + 8) * Nt + gn]) =
                    make_float2(acc[f][j][2], acc[f][j][3]);
            } else {
                int bb  = gn >> 10;
                int pix = gn & 1023;
                float bv0 = bias[gm];
                float bv1 = bias[gm + 8];
                *reinterpret_cast<float2*>(
                    &Cout[((size_t)bb * C_ + gm) * HW_ + pix]) =
                    make_float2(acc[f][j][0] + bv0, acc[f][j][1] + bv0);
                *reinterpret_cast<float2*>(
                    &Cout[((size_t)bb * C_ + gm + 8) * HW_ + pix]) =
                    make_float2(acc[f][j][2] + bv1, acc[f][j][3] + bv1);
            }
        }
    }
}

// ---------------------------------------------------------------------------
// Kernel 3: attention, two-phase flash over key halves (verbatim round-10).
// grid (qchunk=16, head=6, batch=32), 256 threads (8 warps), each warp: 8 q.
// ---------------------------------------------------------------------------
#define KP 68
#define ATTN_SMEM_FLOATS (128 * KP + 128 * 64 + 8 * 1024)
#define ATTN_SMEM_BYTES  (ATTN_SMEM_FLOATS * 4)

__global__ __launch_bounds__(256, 2)
void attn_kernel()
{
    extern __shared__ float sm[];
    float* K_s  = sm;                    // [128][KP]
    float* V_s  = sm + 128 * KP;         // [128][64]
    float* qp_s = V_s + 128 * 64;        // per warp 1024 floats

    const int qc = blockIdx.x;   // 0..15
    const int h  = blockIdx.y;   // 0..5
    const int b  = blockIdx.z;   // 0..31
    const int tid  = threadIdx.x;
    const int w    = tid >> 5;
    const int lane = tid & 31;
    float* qw = qp_s + (w << 10);
    const int qg = qc * 64 + w * 8;

    float mq[8], lq[8];
    u64 acc2[4][2];
#pragma unroll
    for (int qp = 0; qp < 4; ++qp) { acc2[qp][0] = 0ull; acc2[qp][1] = 0ull; }

    for (int half = 0; half < 2; ++half) {
        __syncthreads();
        for (int idx = tid; idx < 128 * 16; idx += 256) {
            int j = idx >> 4, f = idx & 15;
            const float4* kv = reinterpret_cast<const float4*>(
                g_KV + ((size_t)(b * HWK_ + half * 128 + j)) * (2 * INNER) + h * DHEAD);
            *reinterpret_cast<float4*>(K_s + j * KP + f * 4) = kv[f];
            *reinterpret_cast<float4*>(V_s + j * 64 + f * 4) = kv[96 + f];
        }
        __syncthreads();

        const float* qbase = g_Q + ((size_t)(b * HW_ + qg)) * INNER + h * DHEAD;
#pragma unroll
        for (int r = 0; r < 4; ++r) {
            int idx = r * 32 + lane;
            int qn = idx >> 4, f = idx & 15;
            *reinterpret_cast<float4*>(qw + qn * 64 + f * 4) =
                *reinterpret_cast<const float4*>(qbase + (size_t)qn * INNER + f * 4);
        }
        __syncwarp();

        u64 s2[8][4];
#pragma unroll
        for (int qn = 0; qn < 8; ++qn)
#pragma unroll
            for (int jj = 0; jj < 4; ++jj) s2[qn][jj] = 0ull;

#pragma unroll 4
        for (int dq = 0; dq < 16; ++dq) {
            ulonglong2 kv2[4];
#pragma unroll
            for (int jj = 0; jj < 4; ++jj)
                kv2[jj] = *reinterpret_cast<const ulonglong2*>(
                    K_s + (size_t)(jj * 32 + lane) * KP + dq * 4);
#pragma unroll
            for (int g = 0; g < 2; ++g) {
                u64 ql[4], qh[4];
#pragma unroll
                for (int q4 = 0; q4 < 4; ++q4) {
                    ulonglong2 qv = *reinterpret_cast<const ulonglong2*>(
                        qw + (g * 4 + q4) * 64 + dq * 4);
                    ql[q4] = qv.x; qh[q4] = qv.y;
                }
#pragma unroll
                for (int jj = 0; jj < 4; ++jj)
#pragma unroll
                    for (int q4 = 0; q4 < 4; ++q4) {
                        ffma2(s2[g * 4 + q4][jj], ql[q4], kv2[jj].x);
                        ffma2(s2[g * 4 + q4][jj], qh[q4], kv2[jj].y);
                    }
            }
        }
        __syncwarp();

        float resc[8];
#pragma unroll
        for (int qn = 0; qn < 8; ++qn) {
            float s[4];
            float ml = -1e30f;
#pragma unroll
            for (int jj = 0; jj < 4; ++jj) {
                float2 f2 = unpack2(s2[qn][jj]);
                s[jj] = (f2.x + f2.y) * SCALE;
                ml = fmaxf(ml, s[jj]);
            }
#pragma unroll
            for (int o = 16; o > 0; o >>= 1)
                ml = fmaxf(ml, __shfl_xor_sync(0xffffffffu, ml, o));
            float mnew = (half == 0) ? ml : fmaxf(mq[qn], ml);
            float r    = (half == 0) ? 0.f : __expf(mq[qn] - mnew);
            float l = 0.f;
            float* pq = qw + (qn >> 1) * 256 + (qn & 1);
#pragma unroll
            for (int jj = 0; jj < 4; ++jj) {
                float p = __expf(s[jj] - mnew);
                pq[(jj * 32 + lane) * 2] = p;
                l += p;
            }
#pragma unroll
            for (int o = 16; o > 0; o >>= 1)
                l += __shfl_xor_sync(0xffffffffu, l, o);
            lq[qn] = (half == 0) ? l : lq[qn] * r + l;
            mq[qn] = mnew;
            resc[qn] = r;
        }
        __syncwarp();

        if (half == 1) {
#pragma unroll
            for (int qp = 0; qp < 4; ++qp) {
                u64 rr = pack2(resc[2 * qp], resc[2 * qp + 1]);
                acc2[qp][0] = mul2(acc2[qp][0], rr);
                acc2[qp][1] = mul2(acc2[qp][1], rr);
            }
        }

#pragma unroll 4
        for (int j2 = 0; j2 < 64; ++j2) {
            int j = j2 * 2;
            float2 va = *reinterpret_cast<const float2*>(V_s + (size_t)j * 64 + 2 * lane);
            float2 vb = *reinterpret_cast<const float2*>(V_s + (size_t)(j + 1) * 64 + 2 * lane);
            u64 va0 = pack2(va.x, va.x), va1 = pack2(va.y, va.y);
            u64 vb0 = pack2(vb.x, vb.x), vb1 = pack2(vb.y, vb.y);
#pragma unroll
            for (int qp = 0; qp < 4; ++qp) {
                ulonglong2 pv = *reinterpret_cast<const ulonglong2*>(qw + qp * 256 + j * 2);
                ffma2(acc2[qp][0], pv.x, va0);
                ffma2(acc2[qp][1], pv.x, va1);
                ffma2(acc2[qp][0], pv.y, vb0);
                ffma2(acc2[qp][1], pv.y, vb1);
            }
        }
    }

#pragma unroll
    for (int qn = 0; qn < 8; ++qn) {
        int qp = qn >> 1, par = qn & 1;
        float2 f0 = unpack2(acc2[qp][0]);
        float2 f1 = unpack2(acc2[qp][1]);
        float linv = 1.0f / lq[qn];
        float o0 = (par ? f0.y : f0.x) * linv;
        float o1 = (par ? f1.y : f1.x) * linv;
        *reinterpret_cast<float2*>(
            g_O + ((size_t)(b * HW_ + qg + qn)) * INNER + h * DHEAD + 2 * lane) =
            make_float2(o0, o1);
    }
}

// ---------------------------------------------------------------------------
// launcher
// ---------------------------------------------------------------------------
extern "C" void kernel_launch(void* const* d_in, const int* in_sizes, int n_in,
                              void* d_out, int out_size)
{
    (void)in_sizes; (void)n_in; (void)out_size;

    const float* x        = (const float*)d_in[0];
    const float* q_dw     = (const float*)d_in[1];
    const float* q_gamma  = (const float*)d_in[2];
    const float* q_beta   = (const float*)d_in[3];
    const float* q_mean   = (const float*)d_in[4];
    const float* q_var    = (const float*)d_in[5];
    const float* q_pw     = (const float*)d_in[6];
    const float* kv_dw    = (const float*)d_in[7];
    const float* kv_gamma = (const float*)d_in[8];
    const float* kv_beta  = (const float*)d_in[9];
    const float* kv_mean  = (const float*)d_in[10];
    const float* kv_var   = (const float*)d_in[11];
    const float* kv_pw    = (const float*)d_in[12];
    const float* out_w    = (const float*)d_in[13];
    const float* out_b    = (const float*)d_in[14];
    float* out = (float*)d_out;

    void *p_yq, *p_ykv, *p_Q, *p_KV, *p_O;
    cudaGetSymbolAddress(&p_yq,  g_yq);
    cudaGetSymbolAddress(&p_ykv, g_ykv);
    cudaGetSymbolAddress(&p_Q,   g_Q);
    cudaGetSymbolAddress(&p_KV,  g_KV);
    cudaGetSymbolAddress(&p_O,   g_O);

    // 1) depthwise conv + BN, transposed (row-major) activations
    dwbn_kernel<<<dim3(C_ / 8, B_), 256>>>(x,
        q_dw, q_gamma, q_beta, q_mean, q_var,
        kv_dw, kv_gamma, kv_beta, kv_mean, kv_var);

    // 2) Q pointwise (tf32 mma): m=pix (32768), n=ch (384) -> row-major g_Q
    gemm_mma<0><<<dim3(INNER / 128, (B_ * HW_) / 128), 256>>>(
        (const float*)p_yq, q_pw, (float*)p_Q, nullptr, INNER);

    // 3) KV pointwise (tf32 mma): m=pix (8192), n=ch (768) -> row-major g_KV
    gemm_mma<0><<<dim3((2 * INNER) / 128, (B_ * HWK_) / 128), 256>>>(
        (const float*)p_ykv, kv_pw, (float*)p_KV, nullptr, 2 * INNER);

    // 4) attention (two-phase flash, fp32 FFMA2)
    cudaFuncSetAttribute(attn_kernel,
                         cudaFuncAttributeMaxDynamicSharedMemorySize,
                         ATTN_SMEM_BYTES);
    attn_kernel<<<dim3(16, HEADS, B_), 256, ATTN_SMEM_BYTES>>>();

    // 5) output projection (tf32 mma): m=ch (384), n=pix (32768) -> NCHW + bias
    gemm_mma<1><<<dim3(C_ / 128, (B_ * HW_) / 128), 256>>>(
        out_w, (const float*)p_O, out, out_b, 0);
}

// round 13
// speedup vs baseline: 1.8903x; 1.1623x over previous
#include <cuda_runtime.h>
#include <cuda_bf16.h>
#include <cstdint>
#include <cstddef>

// Problem constants
#define B_    32
#define C_    384
#define H_    32
#define W_    32
#define HW_   1024
#define HK_   16
#define WK_   16
#define HWK_  256
#define HEADS 6
#define DHEAD 64
#define INNER 384          // HEADS*DHEAD
#define SCALE 0.125f       // DIM_HEAD^-0.5
#define BN_EPS 1e-5f

typedef unsigned long long u64;

// ---------------------------------------------------------------------------
// tf32 helpers
// ---------------------------------------------------------------------------
__device__ __forceinline__ float to_tf32f(float x) {
    uint32_t r; asm("cvt.rna.tf32.f32 %0, %1;" : "=r"(r) : "f"(x));
    return __uint_as_float(r);
}
__device__ __forceinline__ void mma_tf32(float* d, const uint32_t* a, const uint32_t* b) {
    asm volatile(
        "mma.sync.aligned.m16n8k8.row.col.f32.tf32.tf32.f32 "
        "{%0,%1,%2,%3}, {%4,%5,%6,%7}, {%8,%9}, {%0,%1,%2,%3};"
        : "+f"(d[0]), "+f"(d[1]), "+f"(d[2]), "+f"(d[3])
        : "r"(a[0]), "r"(a[1]), "r"(a[2]), "r"(a[3]), "r"(b[0]), "r"(b[1]));
}

// ---------------------------------------------------------------------------
// Scratch (static device globals; no runtime allocation allowed)
// ---------------------------------------------------------------------------
__device__ float g_yq [(size_t)B_ * HW_ * C_];          // dw+bn out, Q path [pix][c] (tf32-rounded)
__device__ float g_ykv[(size_t)B_ * HWK_ * C_];         // dw+bn out, KV path (tf32-rounded)
__device__ float g_Q  [(size_t)B_ * HW_ * INNER];       // Q row-major (tf32-rounded)
__device__ float g_KV [(size_t)B_ * HWK_ * 2 * INNER];  // KV row-major (tf32-rounded)
__device__ float g_O  [(size_t)B_ * HW_ * INNER];       // attention out (tf32-rounded)

#define WQ_OFF  0
#define WKV_OFF (INNER * C_)                       // 147456
#define WO_OFF  (WQ_OFF + INNER * C_ + 2 * INNER * C_)   // 442368
__device__ float g_w[INNER * C_ + 2 * INNER * C_ + C_ * INNER];  // rounded weights

// ---------------------------------------------------------------------------
// Kernel 0: pre-round weights to tf32 (rna)
// ---------------------------------------------------------------------------
__global__ __launch_bounds__(256)
void prep_weights(const float* __restrict__ q_pw, const float* __restrict__ kv_pw,
                  const float* __restrict__ out_w)
{
    int i = blockIdx.x * 256 + threadIdx.x;
    if (i < WKV_OFF)          g_w[i] = to_tf32f(q_pw[i]);
    else if (i < WO_OFF)      g_w[i] = to_tf32f(kv_pw[i - WKV_OFF]);
    else if (i < WO_OFF + C_ * INNER) g_w[i] = to_tf32f(out_w[i - WO_OFF]);
}

// ---------------------------------------------------------------------------
// Kernel 1: fused depthwise 3x3 (+BN), 8-channel groups, TRANSPOSED outputs,
// tf32-rounded (feeds tensor-core GEMMs).
// ---------------------------------------------------------------------------
__global__ __launch_bounds__(256)
void dwbn_kernel(const float* __restrict__ x,
                 const float* __restrict__ q_dw,  const float* __restrict__ q_gamma,
                 const float* __restrict__ q_beta, const float* __restrict__ q_mean,
                 const float* __restrict__ q_var,
                 const float* __restrict__ kv_dw, const float* __restrict__ kv_gamma,
                 const float* __restrict__ kv_beta, const float* __restrict__ kv_mean,
                 const float* __restrict__ kv_var)
{
    const int g  = blockIdx.x;
    const int b  = blockIdx.y;
    const int c0 = g * 8;
    const int tid = threadIdx.x;

    __shared__ float sx[8][34 * 34];
    __shared__ float wq_s[72], wk_s[72];
    __shared__ float bn_s[32];

    for (int idx = tid; idx < 8 * 1156; idx += 256) {
        int cc = idx / 1156, i = idx - cc * 1156;
        int r = i / 34, col = i - r * 34;
        int iy = r - 1, ix = col - 1;
        float v = 0.f;
        if (iy >= 0 && iy < 32 && ix >= 0 && ix < 32)
            v = x[((size_t)b * C_ + c0 + cc) * HW_ + iy * 32 + ix];
        sx[cc][i] = v;
    }
    if (tid < 72) { wq_s[tid] = q_dw[c0 * 9 + tid]; wk_s[tid] = kv_dw[c0 * 9 + tid]; }
    if (tid < 8) {
        int c = c0 + tid;
        float iq = q_gamma[c] * rsqrtf(q_var[c] + BN_EPS);
        bn_s[tid]      = iq;
        bn_s[8 + tid]  = q_beta[c] - q_mean[c] * iq;
        float ik = kv_gamma[c] * rsqrtf(kv_var[c] + BN_EPS);
        bn_s[16 + tid] = ik;
        bn_s[24 + tid] = kv_beta[c] - kv_mean[c] * ik;
    }
    __syncthreads();

    for (int p = tid; p < HW_; p += 256) {
        int oy = p >> 5, ox = p & 31;
        float o8[8];
#pragma unroll
        for (int cc = 0; cc < 8; ++cc) {
            const float* sp = &sx[cc][oy * 34 + ox];
            float s = 0.f;
#pragma unroll
            for (int r = 0; r < 3; ++r)
#pragma unroll
                for (int ss = 0; ss < 3; ++ss)
                    s += wq_s[cc * 9 + r * 3 + ss] * sp[r * 34 + ss];
            o8[cc] = to_tf32f(s * bn_s[cc] + bn_s[8 + cc]);
        }
        float4* dst = reinterpret_cast<float4*>(g_yq + ((size_t)b * HW_ + p) * C_ + c0);
        dst[0] = make_float4(o8[0], o8[1], o8[2], o8[3]);
        dst[1] = make_float4(o8[4], o8[5], o8[6], o8[7]);
    }

    if (tid < HWK_) {
        int oy = tid >> 4, ox = tid & 15;
        float o8[8];
#pragma unroll
        for (int cc = 0; cc < 8; ++cc) {
            const float* sp = &sx[cc][(2 * oy) * 34 + 2 * ox];
            float s = 0.f;
#pragma unroll
            for (int r = 0; r < 3; ++r)
#pragma unroll
                for (int ss = 0; ss < 3; ++ss)
                    s += wk_s[cc * 9 + r * 3 + ss] * sp[r * 34 + ss];
            o8[cc] = to_tf32f(s * bn_s[16 + cc] + bn_s[24 + cc]);
        }
        float4* dst = reinterpret_cast<float4*>(g_ykv + ((size_t)b * HWK_ + tid) * C_ + c0);
        dst[0] = make_float4(o8[0], o8[1], o8[2], o8[3]);
        dst[1] = make_float4(o8[4], o8[5], o8[6], o8[7]);
    }
}

// ---------------------------------------------------------------------------
// Kernel 2: tensor-core tf32 GEMM via mma.sync.m16n8k8.
// Inputs are PRE-ROUNDED tf32; staging is a pure pairing copy.
//   OUTMODE 0: row-major out (tf32-rounded, feeds attention)
//   OUTMODE 1: NCHW + bias (final output, full fp32)
// ---------------------------------------------------------------------------
template <int OUTMODE>
__global__ __launch_bounds__(256, 2)
void gemm_mma(const float* __restrict__ Amat, const float* __restrict__ Bmat,
              float* __restrict__ Cout, const float* __restrict__ bias, int Nt)
{
    __shared__ float smem[2][2][2][128][10];   // 40960 bytes

    const int tid  = threadIdx.x;
    const int lane = tid & 31;
    const int w    = tid >> 5;
    const int mw   = w & 1;
    const int nw   = w >> 1;
    const int qrow = lane >> 2;
    const int qk   = (lane & 3) * 2;

    int m0, n0;
    if (OUTMODE == 0) { n0 = blockIdx.x * 128; m0 = blockIdx.y * 128; }
    else              { m0 = blockIdx.x * 128; n0 = blockIdx.y * 128; }

    const int srow = tid & 127;
    const int sop  = tid >> 7;
    const float* src = (sop == 0) ? (Amat + (size_t)(m0 + srow) * 384)
                                  : (Bmat + (size_t)(n0 + srow) * 384);

    float acc[4][4][4];
#pragma unroll
    for (int f = 0; f < 4; ++f)
#pragma unroll
        for (int j = 0; j < 4; ++j)
#pragma unroll
            for (int e = 0; e < 4; ++e) acc[f][j][e] = 0.f;

    float4 pf0, pf1, pf2, pf3;
    {
        const float4* gsrc = reinterpret_cast<const float4*>(src);
        pf0 = gsrc[0]; pf1 = gsrc[1]; pf2 = gsrc[2]; pf3 = gsrc[3];
        float2* d0 = reinterpret_cast<float2*>(&smem[sop][0][0][srow][0]);
        float2* d1 = reinterpret_cast<float2*>(&smem[sop][0][1][srow][0]);
        d0[0] = make_float2(pf0.x, pf1.x); d0[1] = make_float2(pf0.y, pf1.y);
        d0[2] = make_float2(pf0.z, pf1.z); d0[3] = make_float2(pf0.w, pf1.w);
        d1[0] = make_float2(pf2.x, pf3.x); d1[1] = make_float2(pf2.y, pf3.y);
        d1[2] = make_float2(pf2.z, pf3.z); d1[3] = make_float2(pf2.w, pf3.w);
    }
    __syncthreads();

    int buf = 0;
    for (int c = 0; c < 24; ++c) {
        if (c + 1 < 24) {
            const float4* gsrc = reinterpret_cast<const float4*>(src + (c + 1) * 16);
            pf0 = gsrc[0]; pf1 = gsrc[1]; pf2 = gsrc[2]; pf3 = gsrc[3];
        }

#pragma unroll
        for (int grp = 0; grp < 2; ++grp) {
            uint32_t a[4][4];
#pragma unroll
            for (int f = 0; f < 4; ++f) {
                float2 lo = *reinterpret_cast<const float2*>(
                    &smem[0][buf][grp][mw * 64 + f * 16 + qrow][qk]);
                float2 hi = *reinterpret_cast<const float2*>(
                    &smem[0][buf][grp][mw * 64 + f * 16 + 8 + qrow][qk]);
                a[f][0] = __float_as_uint(lo.x);
                a[f][1] = __float_as_uint(hi.x);
                a[f][2] = __float_as_uint(lo.y);
                a[f][3] = __float_as_uint(hi.y);
            }
            uint32_t bf[4][2];
#pragma unroll
            for (int j = 0; j < 4; ++j) {
                float2 bb = *reinterpret_cast<const float2*>(
                    &smem[1][buf][grp][nw * 32 + j * 8 + qrow][qk]);
                bf[j][0] = __float_as_uint(bb.x);
                bf[j][1] = __float_as_uint(bb.y);
            }
#pragma unroll
            for (int f = 0; f < 4; ++f)
#pragma unroll
                for (int j = 0; j < 4; ++j)
                    mma_tf32(acc[f][j], a[f], bf[j]);
        }

        if (c + 1 < 24) {
            int nb = buf ^ 1;
            float2* d0 = reinterpret_cast<float2*>(&smem[sop][nb][0][srow][0]);
            float2* d1 = reinterpret_cast<float2*>(&smem[sop][nb][1][srow][0]);
            d0[0] = make_float2(pf0.x, pf1.x); d0[1] = make_float2(pf0.y, pf1.y);
            d0[2] = make_float2(pf0.z, pf1.z); d0[3] = make_float2(pf0.w, pf1.w);
            d1[0] = make_float2(pf2.x, pf3.x); d1[1] = make_float2(pf2.y, pf3.y);
            d1[2] = make_float2(pf2.z, pf3.z); d1[3] = make_float2(pf2.w, pf3.w);
            __syncthreads();
        }
        buf ^= 1;
    }

#pragma unroll
    for (int f = 0; f < 4; ++f) {
#pragma unroll
        for (int j = 0; j < 4; ++j) {
            int gm = m0 + mw * 64 + f * 16 + qrow;
            int gn = n0 + nw * 32 + j * 8 + (lane & 3) * 2;
            if (OUTMODE == 0) {
                *reinterpret_cast<float2*>(&Cout[(size_t)gm * Nt + gn]) =
                    make_float2(to_tf32f(acc[f][j][0]), to_tf32f(acc[f][j][1]));
                *reinterpret_cast<float2*>(&Cout[(size_t)(gm + 8) * Nt + gn]) =
                    make_float2(to_tf32f(acc[f][j][2]), to_tf32f(acc[f][j][3]));
            } else {
                int bb  = gn >> 10;
                int pix = gn & 1023;
                float bv0 = bias[gm];
                float bv1 = bias[gm + 8];
                *reinterpret_cast<float2*>(
                    &Cout[((size_t)bb * C_ + gm) * HW_ + pix]) =
                    make_float2(acc[f][j][0] + bv0, acc[f][j][1] + bv0);
                *reinterpret_cast<float2*>(
                    &Cout[((size_t)bb * C_ + gm + 8) * HW_ + pix]) =
                    make_float2(acc[f][j][2] + bv1, acc[f][j][3] + bv1);
            }
        }
    }
}

// ---------------------------------------------------------------------------
// Kernel 3: attention, full tensor-core (mma.sync tf32).
// grid (qtile=8, head=6, batch=32), 256 threads (8 warps), warp = 16 q-rows.
// Two key-halves flash. S accumulators feed PV A-fragments directly from
// registers (V staged per-group transposed so the layout permutation folds).
// smem: Ks[8][256][10] | Vs[32][64][10] | Qs[8][128][10] = 204800 B.
// ---------------------------------------------------------------------------
#define ATTN_SMEM_BYTES ((8*256*10 + 32*64*10 + 8*128*10) * 4)

__global__ __launch_bounds__(256)
void attn_mma_kernel()
{
    extern __shared__ float sm[];
    float* Ks = sm;                          // [g 8][j 256][10] pairs (d,d+4)
    float* Vs = sm + 8 * 256 * 10;           // [f 32][d 64][10] = V[8f+jw][d] at slot jw
    float* Qs = Vs + 32 * 64 * 10;           // [g 8][m 128][10] pairs (d,d+4), pre-scaled

    const int qt = blockIdx.x;   // 0..7
    const int h  = blockIdx.y;
    const int b  = blockIdx.z;
    const int tid  = threadIdx.x;
    const int w    = tid >> 5;
    const int lane = tid & 31;
    const int r  = lane >> 2;    // 0..7
    const int q4 = lane & 3;
    const int q0 = qt * 128;

    // ---- stage K, V ----
    for (int idx = tid; idx < 256 * 16; idx += 256) {
        int j = idx >> 4, f4 = idx & 15;
        const float4* kvp = reinterpret_cast<const float4*>(
            g_KV + ((size_t)(b * HWK_ + j)) * (2 * INNER) + h * DHEAD);
        float4 kk = kvp[f4];
        float4 vv = kvp[96 + f4];
        int g = f4 >> 1, s = f4 & 1;
        float* kd = Ks + ((g << 8) + j) * 10 + s;
        kd[0] = kk.x; kd[2] = kk.y; kd[4] = kk.z; kd[6] = kk.w;
        float* vd = Vs + (((j >> 3) << 6) + (f4 << 2)) * 10 + (j & 7);
        vd[0] = vv.x; vd[10] = vv.y; vd[20] = vv.z; vd[30] = vv.w;
    }
    // ---- stage Q (pre-scaled by SCALE; exact power of two) ----
    for (int idx = tid; idx < 128 * 16; idx += 256) {
        int m = idx >> 4, f4 = idx & 15;
        float4 qq = reinterpret_cast<const float4*>(
            g_Q + ((size_t)(b * HW_ + q0 + m)) * INNER + h * DHEAD)[f4];
        int g = f4 >> 1, s = f4 & 1;
        float* qd = Qs + ((g << 7) + m) * 10 + s;
        qd[0] = qq.x * SCALE; qd[2] = qq.y * SCALE;
        qd[4] = qq.z * SCALE; qd[6] = qq.w * SCALE;
    }
    __syncthreads();

    float dacc[8][4];
#pragma unroll
    for (int n = 0; n < 8; ++n)
#pragma unroll
        for (int e = 0; e < 4; ++e) dacc[n][e] = 0.f;

    float mrow0 = -1e30f, mrow1 = -1e30f, lrow0 = 0.f, lrow1 = 0.f;

#pragma unroll
    for (int ph = 0; ph < 2; ++ph) {
        // ---- S = Q K^T over 128 keys ----
        float sacc[16][4];
#pragma unroll
        for (int f2 = 0; f2 < 16; ++f2)
#pragma unroll
            for (int e = 0; e < 4; ++e) sacc[f2][e] = 0.f;

#pragma unroll
        for (int g = 0; g < 8; ++g) {
            float2 alo = *reinterpret_cast<const float2*>(
                Qs + ((g << 7) + (w << 4) + r) * 10 + q4 * 2);
            float2 ahi = *reinterpret_cast<const float2*>(
                Qs + ((g << 7) + (w << 4) + 8 + r) * 10 + q4 * 2);
            uint32_t a[4] = { __float_as_uint(alo.x), __float_as_uint(ahi.x),
                              __float_as_uint(alo.y), __float_as_uint(ahi.y) };
#pragma unroll
            for (int f2 = 0; f2 < 16; ++f2) {
                float2 bb = *reinterpret_cast<const float2*>(
                    Ks + ((g << 8) + (ph << 7) + (f2 << 3) + r) * 10 + q4 * 2);
                uint32_t bf[2] = { __float_as_uint(bb.x), __float_as_uint(bb.y) };
                mma_tf32(sacc[f2], a, bf);
            }
        }

        // ---- softmax (rows r and r+8; quad = 4 lanes share a row) ----
        float ml0 = -1e30f, ml1 = -1e30f;
#pragma unroll
        for (int f2 = 0; f2 < 16; ++f2) {
            ml0 = fmaxf(ml0, fmaxf(sacc[f2][0], sacc[f2][1]));
            ml1 = fmaxf(ml1, fmaxf(sacc[f2][2], sacc[f2][3]));
        }
        ml0 = fmaxf(ml0, __shfl_xor_sync(0xffffffffu, ml0, 1));
        ml0 = fmaxf(ml0, __shfl_xor_sync(0xffffffffu, ml0, 2));
        ml1 = fmaxf(ml1, __shfl_xor_sync(0xffffffffu, ml1, 1));
        ml1 = fmaxf(ml1, __shfl_xor_sync(0xffffffffu, ml1, 2));

        float mn0 = (ph == 0) ? ml0 : fmaxf(mrow0, ml0);
        float mn1 = (ph == 0) ? ml1 : fmaxf(mrow1, ml1);
        float rs0 = (ph == 0) ? 0.f : __expf(mrow0 - mn0);
        float rs1 = (ph == 0) ? 0.f : __expf(mrow1 - mn1);

        float ls0 = 0.f, ls1 = 0.f;
#pragma unroll
        for (int f2 = 0; f2 < 16; ++f2) {
            float p0 = __expf(sacc[f2][0] - mn0); ls0 += p0; sacc[f2][0] = to_tf32f(p0);
            float p1 = __expf(sacc[f2][1] - mn0); ls0 += p1; sacc[f2][1] = to_tf32f(p1);
            float p2 = __expf(sacc[f2][2] - mn1); ls1 += p2; sacc[f2][2] = to_tf32f(p2);
            float p3 = __expf(sacc[f2][3] - mn1); ls1 += p3; sacc[f2][3] = to_tf32f(p3);
        }
        ls0 += __shfl_xor_sync(0xffffffffu, ls0, 1);
        ls0 += __shfl_xor_sync(0xffffffffu, ls0, 2);
        ls1 += __shfl_xor_sync(0xffffffffu, ls1, 1);
        ls1 += __shfl_xor_sync(0xffffffffu, ls1, 2);

        if (ph == 0) {
            lrow0 = ls0; lrow1 = ls1;
        } else {
            lrow0 = lrow0 * rs0 + ls0;
            lrow1 = lrow1 * rs1 + ls1;
#pragma unroll
            for (int n = 0; n < 8; ++n) {
                dacc[n][0] *= rs0; dacc[n][1] *= rs0;
                dacc[n][2] *= rs1; dacc[n][3] *= rs1;
            }
        }
        mrow0 = mn0; mrow1 = mn1;

        // ---- D += P V (A-fragments come straight from sacc registers) ----
#pragma unroll
        for (int fg = 0; fg < 16; ++fg) {
            uint32_t a[4] = { __float_as_uint(sacc[fg][0]), __float_as_uint(sacc[fg][2]),
                              __float_as_uint(sacc[fg][1]), __float_as_uint(sacc[fg][3]) };
            int f = (ph << 4) + fg;
#pragma unroll
            for (int n = 0; n < 8; ++n) {
                float2 bb = *reinterpret_cast<const float2*>(
                    Vs + ((f << 6) + (n << 3) + r) * 10 + q4 * 2);
                uint32_t bf[2] = { __float_as_uint(bb.x), __float_as_uint(bb.y) };
                mma_tf32(dacc[n], a, bf);
            }
        }
    }

    // ---- epilogue: normalize, round, write ----
    float li0 = 1.f / lrow0, li1 = 1.f / lrow1;
    const int row0 = b * HW_ + q0 + (w << 4) + r;
#pragma unroll
    for (int n = 0; n < 8; ++n) {
        *reinterpret_cast<float2*>(
            g_O + (size_t)row0 * INNER + h * DHEAD + (n << 3) + q4 * 2) =
            make_float2(to_tf32f(dacc[n][0] * li0), to_tf32f(dacc[n][1] * li0));
        *reinterpret_cast<float2*>(
            g_O + (size_t)(row0 + 8) * INNER + h * DHEAD + (n << 3) + q4 * 2) =
            make_float2(to_tf32f(dacc[n][2] * li1), to_tf32f(dacc[n][3] * li1));
    }
}

// ---------------------------------------------------------------------------
// launcher
// ---------------------------------------------------------------------------
extern "C" void kernel_launch(void* const* d_in, const int* in_sizes, int n_in,
                              void* d_out, int out_size)
{
    (void)in_sizes; (void)n_in; (void)out_size;

    const float* x        = (const float*)d_in[0];
    const float* q_dw     = (const float*)d_in[1];
    const float* q_gamma  = (const float*)d_in[2];
    const float* q_beta   = (const float*)d_in[3];
    const float* q_mean   = (const float*)d_in[4];
    const float* q_var    = (const float*)d_in[5];
    const float* q_pw     = (const float*)d_in[6];
    const float* kv_dw    = (const float*)d_in[7];
    const float* kv_gamma = (const float*)d_in[8];
    const float* kv_beta  = (const float*)d_in[9];
    const float* kv_mean  = (const float*)d_in[10];
    const float* kv_var   = (const float*)d_in[11];
    const float* kv_pw    = (const float*)d_in[12];
    const float* out_w    = (const float*)d_in[13];
    const float* out_b    = (const float*)d_in[14];
    float* out = (float*)d_out;

    void *p_yq, *p_ykv, *p_Q, *p_KV, *p_O, *p_w;
    cudaGetSymbolAddress(&p_yq,  g_yq);
    cudaGetSymbolAddress(&p_ykv, g_ykv);
    cudaGetSymbolAddress(&p_Q,   g_Q);
    cudaGetSymbolAddress(&p_KV,  g_KV);
    cudaGetSymbolAddress(&p_O,   g_O);
    cudaGetSymbolAddress(&p_w,   g_w);
    const float* wbuf = (const float*)p_w;

    // 0) pre-round weights (589824 elems)
    prep_weights<<<(WO_OFF + C_ * INNER + 255) / 256, 256>>>(q_pw, kv_pw, out_w);

    // 1) depthwise conv + BN, transposed tf32-rounded activations
    dwbn_kernel<<<dim3(C_ / 8, B_), 256>>>(x,
        q_dw, q_gamma, q_beta, q_mean, q_var,
        kv_dw, kv_gamma, kv_beta, kv_mean, kv_var);

    // 2) Q pointwise: m=pix (32768), n=ch (384) -> row-major g_Q
    gemm_mma<0><<<dim3(INNER / 128, (B_ * HW_) / 128), 256>>>(
        (const float*)p_yq, wbuf + WQ_OFF, (float*)p_Q, nullptr, INNER);

    // 3) KV pointwise: m=pix (8192), n=ch (768) -> row-major g_KV
    gemm_mma<0><<<dim3((2 * INNER) / 128, (B_ * HWK_) / 128), 256>>>(
        (const float*)p_ykv, wbuf + WKV_OFF, (float*)p_KV, nullptr, 2 * INNER);

    // 4) attention (full tensor-core)
    cudaFuncSetAttribute(attn_mma_kernel,
                         cudaFuncAttributeMaxDynamicSharedMemorySize,
                         ATTN_SMEM_BYTES);
    attn_mma_kernel<<<dim3(8, HEADS, B_), 256, ATTN_SMEM_BYTES>>>();

    // 5) output projection: m=ch (384), n=pix (32768) -> NCHW + bias
    gemm_mma<1><<<dim3(C_ / 128, (B_ * HW_) / 128), 256>>>(
        wbuf + WO_OFF, (const float*)p_O, out, out_b, 0);
}

// round 14
// speedup vs baseline: 2.5606x; 1.3546x over previous
#include <cuda_runtime.h>
#include <cuda_bf16.h>
#include <cstdint>
#include <cstddef>

// Problem constants
#define B_    32
#define C_    384
#define H_    32
#define W_    32
#define HW_   1024
#define HK_   16
#define WK_   16
#define HWK_  256
#define HEADS 6
#define DHEAD 64
#define INNER 384          // HEADS*DHEAD
#define SCALE 0.125f       // DIM_HEAD^-0.5
#define BN_EPS 1e-5f

typedef unsigned long long u64;

// ---------------------------------------------------------------------------
// tf32 helpers
// ---------------------------------------------------------------------------
__device__ __forceinline__ float to_tf32f(float x) {
    uint32_t r; asm("cvt.rna.tf32.f32 %0, %1;" : "=r"(r) : "f"(x));
    return __uint_as_float(r);
}
__device__ __forceinline__ void mma_tf32(float* d, const uint32_t* a, const uint32_t* b) {
    asm volatile(
        "mma.sync.aligned.m16n8k8.row.col.f32.tf32.tf32.f32 "
        "{%0,%1,%2,%3}, {%4,%5,%6,%7}, {%8,%9}, {%0,%1,%2,%3};"
        : "+f"(d[0]), "+f"(d[1]), "+f"(d[2]), "+f"(d[3])
        : "r"(a[0]), "r"(a[1]), "r"(a[2]), "r"(a[3]), "r"(b[0]), "r"(b[1]));
}
__device__ __forceinline__ void ldsm_x4(uint32_t* r, uint32_t addr) {
    asm volatile("ldmatrix.sync.aligned.m8n8.x4.shared.b16 {%0,%1,%2,%3}, [%4];"
        : "=r"(r[0]), "=r"(r[1]), "=r"(r[2]), "=r"(r[3]) : "r"(addr));
}
__device__ __forceinline__ void ldsm_x2(uint32_t* r, uint32_t addr) {
    asm volatile("ldmatrix.sync.aligned.m8n8.x2.shared.b16 {%0,%1}, [%2];"
        : "=r"(r[0]), "=r"(r[1]) : "r"(addr));
}
__device__ __forceinline__ void cp16(uint32_t dst, const void* src) {
    asm volatile("cp.async.ca.shared.global [%0], [%1], 16;" :: "r"(dst), "l"(src));
}

// ---------------------------------------------------------------------------
// Scratch (static device globals; no runtime allocation allowed)
// ---------------------------------------------------------------------------
__device__ float g_yq [(size_t)B_ * HW_ * C_];          // dw+bn out, Q path (tf32-rounded)
__device__ float g_ykv[(size_t)B_ * HWK_ * C_];         // dw+bn out, KV path (tf32-rounded)
__device__ float g_Q  [(size_t)B_ * HW_ * INNER];       // Q row-major (tf32-rounded)
__device__ float g_KV [(size_t)B_ * HWK_ * 2 * INNER];  // KV row-major (tf32-rounded)
__device__ float g_O  [(size_t)B_ * HW_ * INNER];       // attention out (tf32-rounded)

#define WQ_OFF  0
#define WKV_OFF (INNER * C_)                             // 147456
#define WO_OFF  (WQ_OFF + INNER * C_ + 2 * INNER * C_)   // 442368
__device__ float g_w[INNER * C_ + 2 * INNER * C_ + C_ * INNER];

// ---------------------------------------------------------------------------
// Kernel 0: pre-round weights to tf32 (rna)
// ---------------------------------------------------------------------------
__global__ __launch_bounds__(256)
void prep_weights(const float* __restrict__ q_pw, const float* __restrict__ kv_pw,
                  const float* __restrict__ out_w)
{
    int i = blockIdx.x * 256 + threadIdx.x;
    if (i < WKV_OFF)          g_w[i] = to_tf32f(q_pw[i]);
    else if (i < WO_OFF)      g_w[i] = to_tf32f(kv_pw[i - WKV_OFF]);
    else if (i < WO_OFF + C_ * INNER) g_w[i] = to_tf32f(out_w[i - WO_OFF]);
}

// ---------------------------------------------------------------------------
// Kernel 1: fused depthwise 3x3 (+BN), 8-channel groups, transposed tf32 out
// ---------------------------------------------------------------------------
__global__ __launch_bounds__(256)
void dwbn_kernel(const float* __restrict__ x,
                 const float* __restrict__ q_dw,  const float* __restrict__ q_gamma,
                 const float* __restrict__ q_beta, const float* __restrict__ q_mean,
                 const float* __restrict__ q_var,
                 const float* __restrict__ kv_dw, const float* __restrict__ kv_gamma,
                 const float* __restrict__ kv_beta, const float* __restrict__ kv_mean,
                 const float* __restrict__ kv_var)
{
    const int g  = blockIdx.x;
    const int b  = blockIdx.y;
    const int c0 = g * 8;
    const int tid = threadIdx.x;

    __shared__ float sx[8][34 * 34];
    __shared__ float wq_s[72], wk_s[72];
    __shared__ float bn_s[32];

    for (int idx = tid; idx < 8 * 1156; idx += 256) {
        int cc = idx / 1156, i = idx - cc * 1156;
        int r = i / 34, col = i - r * 34;
        int iy = r - 1, ix = col - 1;
        float v = 0.f;
        if (iy >= 0 && iy < 32 && ix >= 0 && ix < 32)
            v = x[((size_t)b * C_ + c0 + cc) * HW_ + iy * 32 + ix];
        sx[cc][i] = v;
    }
    if (tid < 72) { wq_s[tid] = q_dw[c0 * 9 + tid]; wk_s[tid] = kv_dw[c0 * 9 + tid]; }
    if (tid < 8) {
        int c = c0 + tid;
        float iq = q_gamma[c] * rsqrtf(q_var[c] + BN_EPS);
        bn_s[tid]      = iq;
        bn_s[8 + tid]  = q_beta[c] - q_mean[c] * iq;
        float ik = kv_gamma[c] * rsqrtf(kv_var[c] + BN_EPS);
        bn_s[16 + tid] = ik;
        bn_s[24 + tid] = kv_beta[c] - kv_mean[c] * ik;
    }
    __syncthreads();

    for (int p = tid; p < HW_; p += 256) {
        int oy = p >> 5, ox = p & 31;
        float o8[8];
#pragma unroll
        for (int cc = 0; cc < 8; ++cc) {
            const float* sp = &sx[cc][oy * 34 + ox];
            float s = 0.f;
#pragma unroll
            for (int r = 0; r < 3; ++r)
#pragma unroll
                for (int ss = 0; ss < 3; ++ss)
                    s += wq_s[cc * 9 + r * 3 + ss] * sp[r * 34 + ss];
            o8[cc] = to_tf32f(s * bn_s[cc] + bn_s[8 + cc]);
        }
        float4* dst = reinterpret_cast<float4*>(g_yq + ((size_t)b * HW_ + p) * C_ + c0);
        dst[0] = make_float4(o8[0], o8[1], o8[2], o8[3]);
        dst[1] = make_float4(o8[4], o8[5], o8[6], o8[7]);
    }

    if (tid < HWK_) {
        int oy = tid >> 4, ox = tid & 15;
        float o8[8];
#pragma unroll
        for (int cc = 0; cc < 8; ++cc) {
            const float* sp = &sx[cc][(2 * oy) * 34 + 2 * ox];
            float s = 0.f;
#pragma unroll
            for (int r = 0; r < 3; ++r)
#pragma unroll
                for (int ss = 0; ss < 3; ++ss)
                    s += wk_s[cc * 9 + r * 3 + ss] * sp[r * 34 + ss];
            o8[cc] = to_tf32f(s * bn_s[16 + cc] + bn_s[24 + cc]);
        }
        float4* dst = reinterpret_cast<float4*>(g_ykv + ((size_t)b * HWK_ + tid) * C_ + c0);
        dst[0] = make_float4(o8[0], o8[1], o8[2], o8[3]);
        dst[1] = make_float4(o8[4], o8[5], o8[6], o8[7]);
    }
}

// ---------------------------------------------------------------------------
// Kernel 2: tf32 GEMM, cp.async staging + ldmatrix fragments.
//   D[m][n] = sum_k Amat[m][k] * Bmat[n][k], K=384, both row-major, pre-rounded.
//   Tile 128x128, 8 warps each 64x32, k-chunk 16, double-buffered cp.async.
//   smem [buf][op][128][20] floats (16 data + 4 pad; 80B row -> ldmatrix
//   phases conflict-free, cp.async dsts 16B-aligned).
// ---------------------------------------------------------------------------
template <int OUTMODE>
__global__ __launch_bounds__(256, 2)
void gemm_mma(const float* __restrict__ Amat, const float* __restrict__ Bmat,
              float* __restrict__ Cout, const float* __restrict__ bias, int Nt)
{
    __shared__ float smem[2][2][128][20];   // 40960 B

    const int tid  = threadIdx.x;
    const int lane = tid & 31;
    const int w    = tid >> 5;
    const int mw   = w & 1;
    const int nw   = w >> 1;
    const int qrow = lane >> 2;
    const int q4   = lane & 3;

    int m0, n0;
    if (OUTMODE == 0) { n0 = blockIdx.x * 128; m0 = blockIdx.y * 128; }
    else              { m0 = blockIdx.x * 128; n0 = blockIdx.y * 128; }

    const uint32_t sbase = (uint32_t)__cvta_generic_to_shared(&smem[0][0][0][0]);

    // cp.async mapping: thread -> (seg 0..3, row 0..63); 4 copies per chunk
    const int cseg = tid & 3;
    const int crow = tid >> 2;
    const float* aptr = Amat + (size_t)(m0 + crow) * 384 + cseg * 4;
    const float* bptr = Bmat + (size_t)(n0 + crow) * 384 + cseg * 4;
    const uint32_t dstA = sbase + (uint32_t)((crow * 20 + cseg * 4) * 4);
    const uint32_t dstB = dstA + 128 * 80;          // op=1 plane
    const uint32_t BUFSZ = 2 * 128 * 80;            // bytes per buffer

    float acc[4][4][4];
#pragma unroll
    for (int f = 0; f < 4; ++f)
#pragma unroll
        for (int j = 0; j < 4; ++j)
#pragma unroll
            for (int e = 0; e < 4; ++e) acc[f][j][e] = 0.f;

    // issue chunk 0
    {
        cp16(dstA,             aptr);
        cp16(dstA + 64 * 80,   aptr + (size_t)64 * 384);
        cp16(dstB,             bptr);
        cp16(dstB + 64 * 80,   bptr + (size_t)64 * 384);
        asm volatile("cp.async.commit_group;");
    }

    int buf = 0;
    for (int c = 0; c < 24; ++c) {
        if (c + 1 < 24) {
            uint32_t bo = (uint32_t)(buf ^ 1) * BUFSZ;
            const float* an = aptr + (c + 1) * 16;
            const float* bn = bptr + (c + 1) * 16;
            cp16(dstA + bo,           an);
            cp16(dstA + bo + 64 * 80, an + (size_t)64 * 384);
            cp16(dstB + bo,           bn);
            cp16(dstB + bo + 64 * 80, bn + (size_t)64 * 384);
            asm volatile("cp.async.commit_group;");
            asm volatile("cp.async.wait_group 1;");
        } else {
            asm volatile("cp.async.wait_group 0;");
        }
        __syncthreads();

        const uint32_t abase = sbase + (uint32_t)buf * BUFSZ;
        const uint32_t bbase = abase + 128 * 80;
#pragma unroll
        for (int grp = 0; grp < 2; ++grp) {
            uint32_t a[4][4];
#pragma unroll
            for (int f = 0; f < 4; ++f) {
                uint32_t addr = abase
                    + (uint32_t)((mw * 64 + f * 16 + (lane & 15)) * 80)
                    + (uint32_t)(grp * 32 + (lane >> 4) * 16);
                ldsm_x4(a[f], addr);
            }
            uint32_t bf[4][2];
#pragma unroll
            for (int j = 0; j < 4; ++j) {
                uint32_t addr = bbase
                    + (uint32_t)((nw * 32 + j * 8 + (lane & 7)) * 80)
                    + (uint32_t)(grp * 32 + ((lane >> 3) & 1) * 16);
                ldsm_x2(bf[j], addr);
            }
#pragma unroll
            for (int f = 0; f < 4; ++f)
#pragma unroll
                for (int j = 0; j < 4; ++j)
                    mma_tf32(acc[f][j], a[f], bf[j]);
        }
        __syncthreads();
        buf ^= 1;
    }

#pragma unroll
    for (int f = 0; f < 4; ++f) {
#pragma unroll
        for (int j = 0; j < 4; ++j) {
            int gm = m0 + mw * 64 + f * 16 + qrow;
            int gn = n0 + nw * 32 + j * 8 + q4 * 2;
            if (OUTMODE == 0) {
                *reinterpret_cast<float2*>(&Cout[(size_t)gm * Nt + gn]) =
                    make_float2(to_tf32f(acc[f][j][0]), to_tf32f(acc[f][j][1]));
                *reinterpret_cast<float2*>(&Cout[(size_t)(gm + 8) * Nt + gn]) =
                    make_float2(to_tf32f(acc[f][j][2]), to_tf32f(acc[f][j][3]));
            } else {
                int bb  = gn >> 10;
                int pix = gn & 1023;
                float bv0 = bias[gm];
                float bv1 = bias[gm + 8];
                *reinterpret_cast<float2*>(
                    &Cout[((size_t)bb * C_ + gm) * HW_ + pix]) =
                    make_float2(acc[f][j][0] + bv0, acc[f][j][1] + bv0);
                *reinterpret_cast<float2*>(
                    &Cout[((size_t)bb * C_ + gm + 8) * HW_ + pix]) =
                    make_float2(acc[f][j][2] + bv1, acc[f][j][3] + bv1);
            }
        }
    }
}

// ---------------------------------------------------------------------------
// Kernel 3: attention, full tensor-core (verbatim round-12).
// ---------------------------------------------------------------------------
#define ATTN_SMEM_BYTES ((8*256*10 + 32*64*10 + 8*128*10) * 4)

__global__ __launch_bounds__(256)
void attn_mma_kernel()
{
    extern __shared__ float sm[];
    float* Ks = sm;                          // [g 8][j 256][10] pairs (d,d+4)
    float* Vs = sm + 8 * 256 * 10;           // [f 32][d 64][10]
    float* Qs = Vs + 32 * 64 * 10;           // [g 8][m 128][10], pre-scaled

    const int qt = blockIdx.x;
    const int h  = blockIdx.y;
    const int b  = blockIdx.z;
    const int tid  = threadIdx.x;
    const int w    = tid >> 5;
    const int lane = tid & 31;
    const int r  = lane >> 2;
    const int q4 = lane & 3;
    const int q0 = qt * 128;

    for (int idx = tid; idx < 256 * 16; idx += 256) {
        int j = idx >> 4, f4 = idx & 15;
        const float4* kvp = reinterpret_cast<const float4*>(
            g_KV + ((size_t)(b * HWK_ + j)) * (2 * INNER) + h * DHEAD);
        float4 kk = kvp[f4];
        float4 vv = kvp[96 + f4];
        int g = f4 >> 1, s = f4 & 1;
        float* kd = Ks + ((g << 8) + j) * 10 + s;
        kd[0] = kk.x; kd[2] = kk.y; kd[4] = kk.z; kd[6] = kk.w;
        float* vd = Vs + (((j >> 3) << 6) + (f4 << 2)) * 10 + (j & 7);
        vd[0] = vv.x; vd[10] = vv.y; vd[20] = vv.z; vd[30] = vv.w;
    }
    for (int idx = tid; idx < 128 * 16; idx += 256) {
        int m = idx >> 4, f4 = idx & 15;
        float4 qq = reinterpret_cast<const float4*>(
            g_Q + ((size_t)(b * HW_ + q0 + m)) * INNER + h * DHEAD)[f4];
        int g = f4 >> 1, s = f4 & 1;
        float* qd = Qs + ((g << 7) + m) * 10 + s;
        qd[0] = qq.x * SCALE; qd[2] = qq.y * SCALE;
        qd[4] = qq.z * SCALE; qd[6] = qq.w * SCALE;
    }
    __syncthreads();

    float dacc[8][4];
#pragma unroll
    for (int n = 0; n < 8; ++n)
#pragma unroll
        for (int e = 0; e < 4; ++e) dacc[n][e] = 0.f;

    float mrow0 = -1e30f, mrow1 = -1e30f, lrow0 = 0.f, lrow1 = 0.f;

#pragma unroll
    for (int ph = 0; ph < 2; ++ph) {
        float sacc[16][4];
#pragma unroll
        for (int f2 = 0; f2 < 16; ++f2)
#pragma unroll
            for (int e = 0; e < 4; ++e) sacc[f2][e] = 0.f;

#pragma unroll
        for (int g = 0; g < 8; ++g) {
            float2 alo = *reinterpret_cast<const float2*>(
                Qs + ((g << 7) + (w << 4) + r) * 10 + q4 * 2);
            float2 ahi = *reinterpret_cast<const float2*>(
                Qs + ((g << 7) + (w << 4) + 8 + r) * 10 + q4 * 2);
            uint32_t a[4] = { __float_as_uint(alo.x), __float_as_uint(ahi.x),
                              __float_as_uint(alo.y), __float_as_uint(ahi.y) };
#pragma unroll
            for (int f2 = 0; f2 < 16; ++f2) {
                float2 bb = *reinterpret_cast<const float2*>(
                    Ks + ((g << 8) + (ph << 7) + (f2 << 3) + r) * 10 + q4 * 2);
                uint32_t bf[2] = { __float_as_uint(bb.x), __float_as_uint(bb.y) };
                mma_tf32(sacc[f2], a, bf);
            }
        }

        float ml0 = -1e30f, ml1 = -1e30f;
#pragma unroll
        for (int f2 = 0; f2 < 16; ++f2) {
            ml0 = fmaxf(ml0, fmaxf(sacc[f2][0], sacc[f2][1]));
            ml1 = fmaxf(ml1, fmaxf(sacc[f2][2], sacc[f2][3]));
        }
        ml0 = fmaxf(ml0, __shfl_xor_sync(0xffffffffu, ml0, 1));
        ml0 = fmaxf(ml0, __shfl_xor_sync(0xffffffffu, ml0, 2));
        ml1 = fmaxf(ml1, __shfl_xor_sync(0xffffffffu, ml1, 1));
        ml1 = fmaxf(ml1, __shfl_xor_sync(0xffffffffu, ml1, 2));

        float mn0 = (ph == 0) ? ml0 : fmaxf(mrow0, ml0);
        float mn1 = (ph == 0) ? ml1 : fmaxf(mrow1, ml1);
        float rs0 = (ph == 0) ? 0.f : __expf(mrow0 - mn0);
        float rs1 = (ph == 0) ? 0.f : __expf(mrow1 - mn1);

        float ls0 = 0.f, ls1 = 0.f;
#pragma unroll
        for (int f2 = 0; f2 < 16; ++f2) {
            float p0 = __expf(sacc[f2][0] - mn0); ls0 += p0; sacc[f2][0] = to_tf32f(p0);
            float p1 = __expf(sacc[f2][1] - mn0); ls0 += p1; sacc[f2][1] = to_tf32f(p1);
            float p2 = __expf(sacc[f2][2] - mn1); ls1 += p2; sacc[f2][2] = to_tf32f(p2);
            float p3 = __expf(sacc[f2][3] - mn1); ls1 += p3; sacc[f2][3] = to_tf32f(p3);
        }
        ls0 += __shfl_xor_sync(0xffffffffu, ls0, 1);
        ls0 += __shfl_xor_sync(0xffffffffu, ls0, 2);
        ls1 += __shfl_xor_sync(0xffffffffu, ls1, 1);
        ls1 += __shfl_xor_sync(0xffffffffu, ls1, 2);

        if (ph == 0) {
            lrow0 = ls0; lrow1 = ls1;
        } else {
            lrow0 = lrow0 * rs0 + ls0;
            lrow1 = lrow1 * rs1 + ls1;
#pragma unroll
            for (int n = 0; n < 8; ++n) {
                dacc[n][0] *= rs0; dacc[n][1] *= rs0;
                dacc[n][2] *= rs1; dacc[n][3] *= rs1;
            }
        }
        mrow0 = mn0; mrow1 = mn1;

#pragma unroll
        for (int fg = 0; fg < 16; ++fg) {
            uint32_t a[4] = { __float_as_uint(sacc[fg][0]), __float_as_uint(sacc[fg][2]),
                              __float_as_uint(sacc[fg][1]), __float_as_uint(sacc[fg][3]) };
            int f = (ph << 4) + fg;
#pragma unroll
            for (int n = 0; n < 8; ++n) {
                float2 bb = *reinterpret_cast<const float2*>(
                    Vs + ((f << 6) + (n << 3) + r) * 10 + q4 * 2);
                uint32_t bf[2] = { __float_as_uint(bb.x), __float_as_uint(bb.y) };
                mma_tf32(dacc[n], a, bf);
            }
        }
    }

    float li0 = 1.f / lrow0, li1 = 1.f / lrow1;
    const int row0 = b * HW_ + q0 + (w << 4) + r;
#pragma unroll
    for (int n = 0; n < 8; ++n) {
        *reinterpret_cast<float2*>(
            g_O + (size_t)row0 * INNER + h * DHEAD + (n << 3) + q4 * 2) =
            make_float2(to_tf32f(dacc[n][0] * li0), to_tf32f(dacc[n][1] * li0));
        *reinterpret_cast<float2*>(
            g_O + (size_t)(row0 + 8) * INNER + h * DHEAD + (n << 3) + q4 * 2) =
            make_float2(to_tf32f(dacc[n][2] * li1), to_tf32f(dacc[n][3] * li1));
    }
}

// ---------------------------------------------------------------------------
// launcher
// ---------------------------------------------------------------------------
extern "C" void kernel_launch(void* const* d_in, const int* in_sizes, int n_in,
                              void* d_out, int out_size)
{
    (void)in_sizes; (void)n_in; (void)out_size;

    const float* x        = (const float*)d_in[0];
    const float* q_dw     = (const float*)d_in[1];
    const float* q_gamma  = (const float*)d_in[2];
    const float* q_beta   = (const float*)d_in[3];
    const float* q_mean   = (const float*)d_in[4];
    const float* q_var    = (const float*)d_in[5];
    const float* q_pw     = (const float*)d_in[6];
    const float* kv_dw    = (const float*)d_in[7];
    const float* kv_gamma = (const float*)d_in[8];
    const float* kv_beta  = (const float*)d_in[9];
    const float* kv_mean  = (const float*)d_in[10];
    const float* kv_var   = (const float*)d_in[11];
    const float* kv_pw    = (const float*)d_in[12];
    const float* out_w    = (const float*)d_in[13];
    const float* out_b    = (const float*)d_in[14];
    float* out = (float*)d_out;

    void *p_yq, *p_ykv, *p_Q, *p_KV, *p_O, *p_w;
    cudaGetSymbolAddress(&p_yq,  g_yq);
    cudaGetSymbolAddress(&p_ykv, g_ykv);
    cudaGetSymbolAddress(&p_Q,   g_Q);
    cudaGetSymbolAddress(&p_KV,  g_KV);
    cudaGetSymbolAddress(&p_O,   g_O);
    cudaGetSymbolAddress(&p_w,   g_w);
    const float* wbuf = (const float*)p_w;

    // 0) pre-round weights
    prep_weights<<<(WO_OFF + C_ * INNER + 255) / 256, 256>>>(q_pw, kv_pw, out_w);

    // 1) depthwise conv + BN, transposed tf32-rounded activations
    dwbn_kernel<<<dim3(C_ / 8, B_), 256>>>(x,
        q_dw, q_gamma, q_beta, q_mean, q_var,
        kv_dw, kv_gamma, kv_beta, kv_mean, kv_var);

    // 2) Q pointwise: m=pix (32768), n=ch (384) -> row-major g_Q
    gemm_mma<0><<<dim3(INNER / 128, (B_ * HW_) / 128), 256>>>(
        (const float*)p_yq, wbuf + WQ_OFF, (float*)p_Q, nullptr, INNER);

    // 3) KV pointwise: m=pix (8192), n=ch (768) -> row-major g_KV
    gemm_mma<0><<<dim3((2 * INNER) / 128, (B_ * HWK_) / 128), 256>>>(
        (const float*)p_ykv, wbuf + WKV_OFF, (float*)p_KV, nullptr, 2 * INNER);

    // 4) attention (full tensor-core)
    cudaFuncSetAttribute(attn_mma_kernel,
                         cudaFuncAttributeMaxDynamicSharedMemorySize,
                         ATTN_SMEM_BYTES);
    attn_mma_kernel<<<dim3(8, HEADS, B_), 256, ATTN_SMEM_BYTES>>>();

    // 5) output projection: m=ch (384), n=pix (32768) -> NCHW + bias
    gemm_mma<1><<<dim3(C_ / 128, (B_ * HW_) / 128), 256>>>(
        wbuf + WO_OFF, (const float*)p_O, out, out_b, 0);
}

// round 15
// speedup vs baseline: 3.1629x; 1.2352x over previous
#include <cuda_runtime.h>
#include <cuda_bf16.h>
#include <cstdint>
#include <cstddef>

// Problem constants
#define B_    32
#define C_    384
#define H_    32
#define W_    32
#define HW_   1024
#define HK_   16
#define WK_   16
#define HWK_  256
#define HEADS 6
#define DHEAD 64
#define INNER 384          // HEADS*DHEAD
#define SCALE 0.125f       // DIM_HEAD^-0.5
#define BN_EPS 1e-5f

typedef unsigned long long u64;

// ---------------------------------------------------------------------------
// tf32 helpers
// ---------------------------------------------------------------------------
__device__ __forceinline__ float to_tf32f(float x) {
    uint32_t r; asm("cvt.rna.tf32.f32 %0, %1;" : "=r"(r) : "f"(x));
    return __uint_as_float(r);
}
__device__ __forceinline__ void mma_tf32(float* d, const uint32_t* a, const uint32_t* b) {
    asm volatile(
        "mma.sync.aligned.m16n8k8.row.col.f32.tf32.tf32.f32 "
        "{%0,%1,%2,%3}, {%4,%5,%6,%7}, {%8,%9}, {%0,%1,%2,%3};"
        : "+f"(d[0]), "+f"(d[1]), "+f"(d[2]), "+f"(d[3])
        : "r"(a[0]), "r"(a[1]), "r"(a[2]), "r"(a[3]), "r"(b[0]), "r"(b[1]));
}
__device__ __forceinline__ void ldsm_x4(uint32_t* r, uint32_t addr) {
    asm volatile("ldmatrix.sync.aligned.m8n8.x4.shared.b16 {%0,%1,%2,%3}, [%4];"
        : "=r"(r[0]), "=r"(r[1]), "=r"(r[2]), "=r"(r[3]) : "r"(addr));
}
__device__ __forceinline__ void ldsm_x2(uint32_t* r, uint32_t addr) {
    asm volatile("ldmatrix.sync.aligned.m8n8.x2.shared.b16 {%0,%1}, [%2];"
        : "=r"(r[0]), "=r"(r[1]) : "r"(addr));
}
__device__ __forceinline__ void cp16(uint32_t dst, const void* src) {
    asm volatile("cp.async.ca.shared.global [%0], [%1], 16;" :: "r"(dst), "l"(src));
}

// ---------------------------------------------------------------------------
// Scratch (static device globals; no runtime allocation allowed)
// ---------------------------------------------------------------------------
__device__ float g_yq [(size_t)B_ * HW_ * C_];          // dw+bn out, Q path (tf32-rounded)
__device__ float g_ykv[(size_t)B_ * HWK_ * C_];         // dw+bn out, KV path (tf32-rounded)
__device__ float g_Q  [(size_t)B_ * HW_ * INNER];       // Q row-major (tf32-rounded)
__device__ float g_KV [(size_t)B_ * HWK_ * 2 * INNER];  // KV row-major (tf32-rounded)
__device__ float g_O  [(size_t)B_ * HW_ * INNER];       // attention out (tf32-rounded)

#define WQ_OFF  0
#define WKV_OFF (INNER * C_)                             // 147456
#define WO_OFF  (WQ_OFF + INNER * C_ + 2 * INNER * C_)   // 442368
__device__ float g_w[INNER * C_ + 2 * INNER * C_ + C_ * INNER];

// ---------------------------------------------------------------------------
// Kernel 0: pre-round weights to tf32 (rna)
// ---------------------------------------------------------------------------
__global__ __launch_bounds__(256)
void prep_weights(const float* __restrict__ q_pw, const float* __restrict__ kv_pw,
                  const float* __restrict__ out_w)
{
    int i = blockIdx.x * 256 + threadIdx.x;
    if (i < WKV_OFF)          g_w[i] = to_tf32f(q_pw[i]);
    else if (i < WO_OFF)      g_w[i] = to_tf32f(kv_pw[i - WKV_OFF]);
    else if (i < WO_OFF + C_ * INNER) g_w[i] = to_tf32f(out_w[i - WO_OFF]);
}

// ---------------------------------------------------------------------------
// Kernel 1: fused depthwise 3x3 (+BN), 8-channel groups, transposed tf32 out
// ---------------------------------------------------------------------------
__global__ __launch_bounds__(256)
void dwbn_kernel(const float* __restrict__ x,
                 const float* __restrict__ q_dw,  const float* __restrict__ q_gamma,
                 const float* __restrict__ q_beta, const float* __restrict__ q_mean,
                 const float* __restrict__ q_var,
                 const float* __restrict__ kv_dw, const float* __restrict__ kv_gamma,
                 const float* __restrict__ kv_beta, const float* __restrict__ kv_mean,
                 const float* __restrict__ kv_var)
{
    const int g  = blockIdx.x;
    const int b  = blockIdx.y;
    const int c0 = g * 8;
    const int tid = threadIdx.x;

    __shared__ float sx[8][34 * 34];
    __shared__ float wq_s[72], wk_s[72];
    __shared__ float bn_s[32];

    for (int idx = tid; idx < 8 * 1156; idx += 256) {
        int cc = idx / 1156, i = idx - cc * 1156;
        int r = i / 34, col = i - r * 34;
        int iy = r - 1, ix = col - 1;
        float v = 0.f;
        if (iy >= 0 && iy < 32 && ix >= 0 && ix < 32)
            v = x[((size_t)b * C_ + c0 + cc) * HW_ + iy * 32 + ix];
        sx[cc][i] = v;
    }
    if (tid < 72) { wq_s[tid] = q_dw[c0 * 9 + tid]; wk_s[tid] = kv_dw[c0 * 9 + tid]; }
    if (tid < 8) {
        int c = c0 + tid;
        float iq = q_gamma[c] * rsqrtf(q_var[c] + BN_EPS);
        bn_s[tid]      = iq;
        bn_s[8 + tid]  = q_beta[c] - q_mean[c] * iq;
        float ik = kv_gamma[c] * rsqrtf(kv_var[c] + BN_EPS);
        bn_s[16 + tid] = ik;
        bn_s[24 + tid] = kv_beta[c] - kv_mean[c] * ik;
    }
    __syncthreads();

    for (int p = tid; p < HW_; p += 256) {
        int oy = p >> 5, ox = p & 31;
        float o8[8];
#pragma unroll
        for (int cc = 0; cc < 8; ++cc) {
            const float* sp = &sx[cc][oy * 34 + ox];
            float s = 0.f;
#pragma unroll
            for (int r = 0; r < 3; ++r)
#pragma unroll
                for (int ss = 0; ss < 3; ++ss)
                    s += wq_s[cc * 9 + r * 3 + ss] * sp[r * 34 + ss];
            o8[cc] = to_tf32f(s * bn_s[cc] + bn_s[8 + cc]);
        }
        float4* dst = reinterpret_cast<float4*>(g_yq + ((size_t)b * HW_ + p) * C_ + c0);
        dst[0] = make_float4(o8[0], o8[1], o8[2], o8[3]);
        dst[1] = make_float4(o8[4], o8[5], o8[6], o8[7]);
    }

    if (tid < HWK_) {
        int oy = tid >> 4, ox = tid & 15;
        float o8[8];
#pragma unroll
        for (int cc = 0; cc < 8; ++cc) {
            const float* sp = &sx[cc][(2 * oy) * 34 + 2 * ox];
            float s = 0.f;
#pragma unroll
            for (int r = 0; r < 3; ++r)
#pragma unroll
                for (int ss = 0; ss < 3; ++ss)
                    s += wk_s[cc * 9 + r * 3 + ss] * sp[r * 34 + ss];
            o8[cc] = to_tf32f(s * bn_s[16 + cc] + bn_s[24 + cc]);
        }
        float4* dst = reinterpret_cast<float4*>(g_ykv + ((size_t)b * HWK_ + tid) * C_ + c0);
        dst[0] = make_float4(o8[0], o8[1], o8[2], o8[3]);
        dst[1] = make_float4(o8[4], o8[5], o8[6], o8[7]);
    }
}

// ---------------------------------------------------------------------------
// Kernel 2: tf32 GEMM, cp.async staging + ldmatrix fragments (round-13).
// ---------------------------------------------------------------------------
template <int OUTMODE>
__global__ __launch_bounds__(256, 2)
void gemm_mma(const float* __restrict__ Amat, const float* __restrict__ Bmat,
              float* __restrict__ Cout, const float* __restrict__ bias, int Nt)
{
    __shared__ float smem[2][2][128][20];   // 40960 B

    const int tid  = threadIdx.x;
    const int lane = tid & 31;
    const int w    = tid >> 5;
    const int mw   = w & 1;
    const int nw   = w >> 1;
    const int qrow = lane >> 2;
    const int q4   = lane & 3;

    int m0, n0;
    if (OUTMODE == 0) { n0 = blockIdx.x * 128; m0 = blockIdx.y * 128; }
    else              { m0 = blockIdx.x * 128; n0 = blockIdx.y * 128; }

    const uint32_t sbase = (uint32_t)__cvta_generic_to_shared(&smem[0][0][0][0]);

    const int cseg = tid & 3;
    const int crow = tid >> 2;
    const float* aptr = Amat + (size_t)(m0 + crow) * 384 + cseg * 4;
    const float* bptr = Bmat + (size_t)(n0 + crow) * 384 + cseg * 4;
    const uint32_t dstA = sbase + (uint32_t)((crow * 20 + cseg * 4) * 4);
    const uint32_t dstB = dstA + 128 * 80;
    const uint32_t BUFSZ = 2 * 128 * 80;

    float acc[4][4][4];
#pragma unroll
    for (int f = 0; f < 4; ++f)
#pragma unroll
        for (int j = 0; j < 4; ++j)
#pragma unroll
            for (int e = 0; e < 4; ++e) acc[f][j][e] = 0.f;

    {
        cp16(dstA,             aptr);
        cp16(dstA + 64 * 80,   aptr + (size_t)64 * 384);
        cp16(dstB,             bptr);
        cp16(dstB + 64 * 80,   bptr + (size_t)64 * 384);
        asm volatile("cp.async.commit_group;");
    }

    int buf = 0;
    for (int c = 0; c < 24; ++c) {
        if (c + 1 < 24) {
            uint32_t bo = (uint32_t)(buf ^ 1) * BUFSZ;
            const float* an = aptr + (c + 1) * 16;
            const float* bn = bptr + (c + 1) * 16;
            cp16(dstA + bo,           an);
            cp16(dstA + bo + 64 * 80, an + (size_t)64 * 384);
            cp16(dstB + bo,           bn);
            cp16(dstB + bo + 64 * 80, bn + (size_t)64 * 384);
            asm volatile("cp.async.commit_group;");
            asm volatile("cp.async.wait_group 1;");
        } else {
            asm volatile("cp.async.wait_group 0;");
        }
        __syncthreads();

        const uint32_t abase = sbase + (uint32_t)buf * BUFSZ;
        const uint32_t bbase = abase + 128 * 80;
#pragma unroll
        for (int grp = 0; grp < 2; ++grp) {
            uint32_t a[4][4];
#pragma unroll
            for (int f = 0; f < 4; ++f) {
                uint32_t addr = abase
                    + (uint32_t)((mw * 64 + f * 16 + (lane & 15)) * 80)
                    + (uint32_t)(grp * 32 + (lane >> 4) * 16);
                ldsm_x4(a[f], addr);
            }
            uint32_t bf[4][2];
#pragma unroll
            for (int j = 0; j < 4; ++j) {
                uint32_t addr = bbase
                    + (uint32_t)((nw * 32 + j * 8 + (lane & 7)) * 80)
                    + (uint32_t)(grp * 32 + ((lane >> 3) & 1) * 16);
                ldsm_x2(bf[j], addr);
            }
#pragma unroll
            for (int f = 0; f < 4; ++f)
#pragma unroll
                for (int j = 0; j < 4; ++j)
                    mma_tf32(acc[f][j], a[f], bf[j]);
        }
        __syncthreads();
        buf ^= 1;
    }

#pragma unroll
    for (int f = 0; f < 4; ++f) {
#pragma unroll
        for (int j = 0; j < 4; ++j) {
            int gm = m0 + mw * 64 + f * 16 + qrow;
            int gn = n0 + nw * 32 + j * 8 + q4 * 2;
            if (OUTMODE == 0) {
                *reinterpret_cast<float2*>(&Cout[(size_t)gm * Nt + gn]) =
                    make_float2(to_tf32f(acc[f][j][0]), to_tf32f(acc[f][j][1]));
                *reinterpret_cast<float2*>(&Cout[(size_t)(gm + 8) * Nt + gn]) =
                    make_float2(to_tf32f(acc[f][j][2]), to_tf32f(acc[f][j][3]));
            } else {
                int bb  = gn >> 10;
                int pix = gn & 1023;
                float bv0 = bias[gm];
                float bv1 = bias[gm + 8];
                *reinterpret_cast<float2*>(
                    &Cout[((size_t)bb * C_ + gm) * HW_ + pix]) =
                    make_float2(acc[f][j][0] + bv0, acc[f][j][1] + bv0);
                *reinterpret_cast<float2*>(
                    &Cout[((size_t)bb * C_ + gm + 8) * HW_ + pix]) =
                    make_float2(acc[f][j][2] + bv1, acc[f][j][3] + bv1);
            }
        }
    }
}

// ---------------------------------------------------------------------------
// Kernel 3: attention, full tensor-core, 512 threads / 256-query tiles.
// grid (qtile=4, head=6, batch=32). Warp w handles q-rows w*16..w*16+15.
// Layouts (conflict-free fragment loads):
//   Ks/Qs: [g 8 | stride 2056][row 256][8]   (pair (d,d+4) at offs 2q4,2q4+1)
//   Vs:    [f 32 | stride 552][jw 8 | stride 68][d 64]
// smem total = (2*16448 + 17664) * 4 = 202240 B -> 1 CTA/SM, 4 warps/SMSP.
// ---------------------------------------------------------------------------
#define KQ_G_STRIDE 2056
#define V_F_STRIDE  552
#define V_J_STRIDE  68
#define ATTN_SMEM_BYTES ((2 * 8 * KQ_G_STRIDE + 32 * V_F_STRIDE) * 4)

__global__ __launch_bounds__(512)
void attn_mma_kernel()
{
    extern __shared__ float sm[];
    float* Ks = sm;                            // 8 * 2056
    float* Qs = sm + 8 * KQ_G_STRIDE;          // 8 * 2056
    float* Vs = Qs + 8 * KQ_G_STRIDE;          // 32 * 552

    const int qt = blockIdx.x;   // 0..3
    const int h  = blockIdx.y;
    const int b  = blockIdx.z;
    const int tid  = threadIdx.x;
    const int w    = tid >> 5;   // 0..15
    const int lane = tid & 31;
    const int r  = lane >> 2;
    const int q4 = lane & 3;
    const int q0 = qt * 256;

    // ---- stage K, V (256 keys) ----
    for (int idx = tid; idx < 256 * 16; idx += 512) {
        int j = idx >> 4, f4 = idx & 15;
        const float4* kvp = reinterpret_cast<const float4*>(
            g_KV + ((size_t)(b * HWK_ + j)) * (2 * INNER) + h * DHEAD);
        float4 kk = kvp[f4];
        float4 vv = kvp[96 + f4];
        int g = f4 >> 1, s = f4 & 1;
        float* kd = Ks + g * KQ_G_STRIDE + j * 8 + s;
        kd[0] = kk.x; kd[2] = kk.y; kd[4] = kk.z; kd[6] = kk.w;
        *reinterpret_cast<float4*>(
            Vs + (j >> 3) * V_F_STRIDE + (j & 7) * V_J_STRIDE + (f4 << 2)) = vv;
    }
    // ---- stage Q (256 queries, pre-scaled) ----
    for (int idx = tid; idx < 256 * 16; idx += 512) {
        int m = idx >> 4, f4 = idx & 15;
        float4 qq = reinterpret_cast<const float4*>(
            g_Q + ((size_t)(b * HW_ + q0 + m)) * INNER + h * DHEAD)[f4];
        int g = f4 >> 1, s = f4 & 1;
        float* qd = Qs + g * KQ_G_STRIDE + m * 8 + s;
        qd[0] = qq.x * SCALE; qd[2] = qq.y * SCALE;
        qd[4] = qq.z * SCALE; qd[6] = qq.w * SCALE;
    }
    __syncthreads();

    float dacc[8][4];
#pragma unroll
    for (int n = 0; n < 8; ++n)
#pragma unroll
        for (int e = 0; e < 4; ++e) dacc[n][e] = 0.f;

    float mrow0 = -1e30f, mrow1 = -1e30f, lrow0 = 0.f, lrow1 = 0.f;

#pragma unroll
    for (int ph = 0; ph < 2; ++ph) {
        // ---- S = Q K^T over 128 keys ----
        float sacc[16][4];
#pragma unroll
        for (int f2 = 0; f2 < 16; ++f2)
#pragma unroll
            for (int e = 0; e < 4; ++e) sacc[f2][e] = 0.f;

#pragma unroll
        for (int g = 0; g < 8; ++g) {
            float2 alo = *reinterpret_cast<const float2*>(
                Qs + g * KQ_G_STRIDE + ((w << 4) + r) * 8 + q4 * 2);
            float2 ahi = *reinterpret_cast<const float2*>(
                Qs + g * KQ_G_STRIDE + ((w << 4) + 8 + r) * 8 + q4 * 2);
            uint32_t a[4] = { __float_as_uint(alo.x), __float_as_uint(ahi.x),
                              __float_as_uint(alo.y), __float_as_uint(ahi.y) };
#pragma unroll
            for (int f2 = 0; f2 < 16; ++f2) {
                float2 bb = *reinterpret_cast<const float2*>(
                    Ks + g * KQ_G_STRIDE + ((ph << 7) + (f2 << 3) + r) * 8 + q4 * 2);
                uint32_t bf[2] = { __float_as_uint(bb.x), __float_as_uint(bb.y) };
                mma_tf32(sacc[f2], a, bf);
            }
        }

        // ---- softmax (rows r and r+8; quad shares a row) ----
        float ml0 = -1e30f, ml1 = -1e30f;
#pragma unroll
        for (int f2 = 0; f2 < 16; ++f2) {
            ml0 = fmaxf(ml0, fmaxf(sacc[f2][0], sacc[f2][1]));
            ml1 = fmaxf(ml1, fmaxf(sacc[f2][2], sacc[f2][3]));
        }
        ml0 = fmaxf(ml0, __shfl_xor_sync(0xffffffffu, ml0, 1));
        ml0 = fmaxf(ml0, __shfl_xor_sync(0xffffffffu, ml0, 2));
        ml1 = fmaxf(ml1, __shfl_xor_sync(0xffffffffu, ml1, 1));
        ml1 = fmaxf(ml1, __shfl_xor_sync(0xffffffffu, ml1, 2));

        float mn0 = (ph == 0) ? ml0 : fmaxf(mrow0, ml0);
        float mn1 = (ph == 0) ? ml1 : fmaxf(mrow1, ml1);
        float rs0 = (ph == 0) ? 0.f : __expf(mrow0 - mn0);
        float rs1 = (ph == 0) ? 0.f : __expf(mrow1 - mn1);

        float ls0 = 0.f, ls1 = 0.f;
#pragma unroll
        for (int f2 = 0; f2 < 16; ++f2) {
            float p0 = __expf(sacc[f2][0] - mn0); ls0 += p0; sacc[f2][0] = to_tf32f(p0);
            float p1 = __expf(sacc[f2][1] - mn0); ls0 += p1; sacc[f2][1] = to_tf32f(p1);
            float p2 = __expf(sacc[f2][2] - mn1); ls1 += p2; sacc[f2][2] = to_tf32f(p2);
            float p3 = __expf(sacc[f2][3] - mn1); ls1 += p3; sacc[f2][3] = to_tf32f(p3);
        }
        ls0 += __shfl_xor_sync(0xffffffffu, ls0, 1);
        ls0 += __shfl_xor_sync(0xffffffffu, ls0, 2);
        ls1 += __shfl_xor_sync(0xffffffffu, ls1, 1);
        ls1 += __shfl_xor_sync(0xffffffffu, ls1, 2);

        if (ph == 0) {
            lrow0 = ls0; lrow1 = ls1;
        } else {
            lrow0 = lrow0 * rs0 + ls0;
            lrow1 = lrow1 * rs1 + ls1;
#pragma unroll
            for (int n = 0; n < 8; ++n) {
                dacc[n][0] *= rs0; dacc[n][1] *= rs0;
                dacc[n][2] *= rs1; dacc[n][3] *= rs1;
            }
        }
        mrow0 = mn0; mrow1 = mn1;

        // ---- D += P V (A-fragments straight from sacc registers) ----
#pragma unroll
        for (int fg = 0; fg < 16; ++fg) {
            uint32_t a[4] = { __float_as_uint(sacc[fg][0]), __float_as_uint(sacc[fg][2]),
                              __float_as_uint(sacc[fg][1]), __float_as_uint(sacc[fg][3]) };
            int f = (ph << 4) + fg;
            const float* vb0 = Vs + f * V_F_STRIDE + (q4 * 2) * V_J_STRIDE + r;
#pragma unroll
            for (int n = 0; n < 8; ++n) {
                uint32_t bf[2] = { __float_as_uint(vb0[(n << 3)]),
                                   __float_as_uint(vb0[(n << 3) + V_J_STRIDE]) };
                mma_tf32(dacc[n], a, bf);
            }
        }
    }

    // ---- epilogue ----
    float li0 = 1.f / lrow0, li1 = 1.f / lrow1;
    const int row0 = b * HW_ + q0 + (w << 4) + r;
#pragma unroll
    for (int n = 0; n < 8; ++n) {
        *reinterpret_cast<float2*>(
            g_O + (size_t)row0 * INNER + h * DHEAD + (n << 3) + q4 * 2) =
            make_float2(to_tf32f(dacc[n][0] * li0), to_tf32f(dacc[n][1] * li0));
        *reinterpret_cast<float2*>(
            g_O + (size_t)(row0 + 8) * INNER + h * DHEAD + (n << 3) + q4 * 2) =
            make_float2(to_tf32f(dacc[n][2] * li1), to_tf32f(dacc[n][3] * li1));
    }
}

// ---------------------------------------------------------------------------
// launcher
// ---------------------------------------------------------------------------
extern "C" void kernel_launch(void* const* d_in, const int* in_sizes, int n_in,
                              void* d_out, int out_size)
{
    (void)in_sizes; (void)n_in; (void)out_size;

    const float* x        = (const float*)d_in[0];
    const float* q_dw     = (const float*)d_in[1];
    const float* q_gamma  = (const float*)d_in[2];
    const float* q_beta   = (const float*)d_in[3];
    const float* q_mean   = (const float*)d_in[4];
    const float* q_var    = (const float*)d_in[5];
    const float* q_pw     = (const float*)d_in[6];
    const float* kv_dw    = (const float*)d_in[7];
    const float* kv_gamma = (const float*)d_in[8];
    const float* kv_beta  = (const float*)d_in[9];
    const float* kv_mean  = (const float*)d_in[10];
    const float* kv_var   = (const float*)d_in[11];
    const float* kv_pw    = (const float*)d_in[12];
    const float* out_w    = (const float*)d_in[13];
    const float* out_b    = (const float*)d_in[14];
    float* out = (float*)d_out;

    void *p_yq, *p_ykv, *p_Q, *p_KV, *p_O, *p_w;
    cudaGetSymbolAddress(&p_yq,  g_yq);
    cudaGetSymbolAddress(&p_ykv, g_ykv);
    cudaGetSymbolAddress(&p_Q,   g_Q);
    cudaGetSymbolAddress(&p_KV,  g_KV);
    cudaGetSymbolAddress(&p_O,   g_O);
    cudaGetSymbolAddress(&p_w,   g_w);
    const float* wbuf = (const float*)p_w;

    // 0) pre-round weights
    prep_weights<<<(WO_OFF + C_ * INNER + 255) / 256, 256>>>(q_pw, kv_pw, out_w);

    // 1) depthwise conv + BN, transposed tf32-rounded activations
    dwbn_kernel<<<dim3(C_ / 8, B_), 256>>>(x,
        q_dw, q_gamma, q_beta, q_mean, q_var,
        kv_dw, kv_gamma, kv_beta, kv_mean, kv_var);

    // 2) Q pointwise: m=pix (32768), n=ch (384) -> row-major g_Q
    gemm_mma<0><<<dim3(INNER / 128, (B_ * HW_) / 128), 256>>>(
        (const float*)p_yq, wbuf + WQ_OFF, (float*)p_Q, nullptr, INNER);

    // 3) KV pointwise: m=pix (8192), n=ch (768) -> row-major g_KV
    gemm_mma<0><<<dim3((2 * INNER) / 128, (B_ * HWK_) / 128), 256>>>(
        (const float*)p_ykv, wbuf + WKV_OFF, (float*)p_KV, nullptr, 2 * INNER);

    // 4) attention (full tensor-core, 512 threads)
    cudaFuncSetAttribute(attn_mma_kernel,
                         cudaFuncAttributeMaxDynamicSharedMemorySize,
                         ATTN_SMEM_BYTES);
    attn_mma_kernel<<<dim3(4, HEADS, B_), 512, ATTN_SMEM_BYTES>>>();

    // 5) output projection: m=ch (384), n=pix (32768) -> NCHW + bias
    gemm_mma<1><<<dim3(C_ / 128, (B_ * HW_) / 128), 256>>>(
        wbuf + WO_OFF, (const float*)p_O, out, out_b, 0);
}